// round 1
// baseline (speedup 1.0000x reference)
#include <cuda_runtime.h>
#include <cstdint>

#define BATCH 32
#define TSEQ  512
#define HDIM  1024
#define G4    4096
#define NBLK  128
#define NTHR  256

// ---------------- scratch (device globals: no allocation allowed) ----------------
__device__ float g_gx[(size_t)BATCH * TSEQ * G4];   // 256 MB: precomputed gx for current layer
__device__ float g_h0[(size_t)BATCH * TSEQ * HDIM]; // 64 MB: layer-0 hidden sequence
__device__ float g_gates[BATCH * G4];               // per-step gates scratch
__device__ float g_h[BATCH * HDIM];                 // recurrent h state
__device__ float g_c[BATCH * HDIM];                 // recurrent c state
__device__ unsigned g_barcnt = 0;
__device__ volatile unsigned g_bargen = 0;

// ---------------- helpers ----------------
__device__ __forceinline__ void ffma2(unsigned long long& d, unsigned long long a,
                                      unsigned long long b) {
    asm("fma.rn.f32x2 %0, %1, %2, %0;" : "+l"(d) : "l"(a), "l"(b));
}
__device__ __forceinline__ float f2sum(unsigned long long v) {
    float lo, hi;
    asm("mov.b64 {%0, %1}, %2;" : "=f"(lo), "=f"(hi) : "l"(v));
    return lo + hi;
}
__device__ __forceinline__ float sigmoidf_(float x) {
    return 1.0f / (1.0f + __expf(-x));
}

// gen-based device-wide barrier; safe because all NBLK blocks are co-resident
// (128 blocks <= 148 SMs, 1 block/SM guaranteed by __launch_bounds__(256,1)).
__device__ __forceinline__ void grid_sync() {
    __threadfence();   // every thread publishes its global writes
    __syncthreads();
    if (threadIdx.x == 0) {
        unsigned gen = g_bargen;
        if (atomicAdd(&g_barcnt, 1u) == NBLK - 1u) {
            g_barcnt = 0u;
            __threadfence();
            g_bargen = gen + 1u;
        } else {
            while (g_bargen == gen) { }
            __threadfence();
        }
    }
    __syncthreads();
}

__device__ __forceinline__ float2 block_reduce2(float a, float b, float* sA, float* sB) {
    int tid = threadIdx.x;
    sA[tid] = a; sB[tid] = b;
    __syncthreads();
    #pragma unroll
    for (int s = NTHR / 2; s > 0; s >>= 1) {
        if (tid < s) { sA[tid] += sA[tid + s]; sB[tid] += sB[tid + s]; }
        __syncthreads();
    }
    float2 r = make_float2(sA[0], sB[0]);
    __syncthreads();
    return r;
}

// ---------------- big parallel GEMM: C[MxN] = A[MxK] * B[NxK]^T + bias ----------------
// Tiles: 64x64, K-tile 16, 256 threads, 4x4 per thread, FFMA2 inner loop.
__global__ void __launch_bounds__(256) sgemm_tn_bias(
    const float* __restrict__ A, const float* __restrict__ Bm,
    const float* __restrict__ bias, float* __restrict__ C,
    int M, int N, int K)
{
    __shared__ float2 As2[8][65];
    __shared__ float2 Bs2[8][65];

    int tid = threadIdx.x;
    int n0 = blockIdx.x * 64;
    int m0 = blockIdx.y * 64;
    int tx = tid & 15;        // col lane
    int ty = tid >> 4;        // row lane

    unsigned long long acc[4][4] = {};

    int la_m = tid >> 2;            // 0..63
    int la_k = (tid & 3) * 4;       // 0,4,8,12
    const float* Aptr = A + (size_t)(m0 + la_m) * K + la_k;
    const float* Bptr = Bm + (size_t)(n0 + la_m) * K + la_k;
    int kq = tid & 3;

    for (int k0 = 0; k0 < K; k0 += 16) {
        float4 av = *reinterpret_cast<const float4*>(Aptr + k0);
        float4 bv = *reinterpret_cast<const float4*>(Bptr + k0);
        As2[2 * kq][la_m]     = make_float2(av.x, av.y);
        As2[2 * kq + 1][la_m] = make_float2(av.z, av.w);
        Bs2[2 * kq][la_m]     = make_float2(bv.x, bv.y);
        Bs2[2 * kq + 1][la_m] = make_float2(bv.z, bv.w);
        __syncthreads();
        #pragma unroll
        for (int kp = 0; kp < 8; kp++) {
            unsigned long long a2[4], b2[4];
            #pragma unroll
            for (int i = 0; i < 4; i++)
                a2[i] = *reinterpret_cast<const unsigned long long*>(&As2[kp][ty + 16 * i]);
            #pragma unroll
            for (int j = 0; j < 4; j++)
                b2[j] = *reinterpret_cast<const unsigned long long*>(&Bs2[kp][tx + 16 * j]);
            #pragma unroll
            for (int i = 0; i < 4; i++)
                #pragma unroll
                for (int j = 0; j < 4; j++)
                    ffma2(acc[i][j], a2[i], b2[j]);
        }
        __syncthreads();
    }

    #pragma unroll
    for (int i = 0; i < 4; i++) {
        int m = m0 + ty + 16 * i;
        #pragma unroll
        for (int j = 0; j < 4; j++) {
            int n = n0 + tx + 16 * j;
            C[(size_t)m * N + n] = f2sum(acc[i][j]) + bias[n];
        }
    }
}

// ---------------- persistent recurrent kernel (one layer, all T steps) ----------------
// Phase A: all 128 blocks compute gh = h @ U^T for their 32 columns; write
//          gates = gx + gh + gx*gh to g_gates.   [grid barrier]
// Phase B: blocks 0..31 (one per batch row) do LN(gates), gate activations,
//          cell update, LN(c), h; write h to state + output.   [grid barrier]
__global__ void __launch_bounds__(NTHR, 1) milstm_seq(
    const float* __restrict__ gx, const float* __restrict__ U,
    const float* __restrict__ lngw, const float* __restrict__ lngb,
    const float* __restrict__ lncw, const float* __restrict__ lncb,
    float* __restrict__ out)
{
    __shared__ float2 hs2[16][33];
    __shared__ float2 us2[16][33];
    __shared__ float redA[NTHR];
    __shared__ float redB[NTHR];

    int tid = threadIdx.x;
    int bid = blockIdx.x;

    // zero-init state
    {
        int i = bid * NTHR + tid;    // NBLK*NTHR == 32768 == BATCH*HDIM
        g_h[i] = 0.0f;
        g_c[i] = 0.0f;
    }
    grid_sync();

    int tr = tid & 15;    // row base: rows tr, tr+16
    int tc = tid >> 4;    // col base: cols jb+tc, jb+tc+16
    int jb = bid * 32;

    for (int t = 0; t < TSEQ; ++t) {
        // ---- phase A: gh GEMM (32 rows x 32 cols, K=1024) ----
        unsigned long long acc00 = 0, acc01 = 0, acc10 = 0, acc11 = 0;
        for (int k0 = 0; k0 < HDIM; k0 += 32) {
            #pragma unroll
            for (int q = 0; q < 2; q++) {
                int idx = tid + q * NTHR;      // 0..511
                int rr = idx >> 4;             // 0..31
                int kp = idx & 15;             // 0..15
                hs2[kp][rr] = *reinterpret_cast<const float2*>(
                    &g_h[rr * HDIM + k0 + 2 * kp]);
                us2[kp][rr] = *reinterpret_cast<const float2*>(
                    &U[(size_t)(jb + rr) * HDIM + k0 + 2 * kp]);
            }
            __syncthreads();
            #pragma unroll
            for (int kp = 0; kp < 16; kp++) {
                unsigned long long a0 = *reinterpret_cast<const unsigned long long*>(&hs2[kp][tr]);
                unsigned long long a1 = *reinterpret_cast<const unsigned long long*>(&hs2[kp][tr + 16]);
                unsigned long long b0 = *reinterpret_cast<const unsigned long long*>(&us2[kp][tc]);
                unsigned long long b1 = *reinterpret_cast<const unsigned long long*>(&us2[kp][tc + 16]);
                ffma2(acc00, a0, b0); ffma2(acc01, a0, b1);
                ffma2(acc10, a1, b0); ffma2(acc11, a1, b1);
            }
            __syncthreads();
        }
        // gates = gx + gh + gx*gh
        {
            float gh00 = f2sum(acc00), gh01 = f2sum(acc01);
            float gh10 = f2sum(acc10), gh11 = f2sum(acc11);
            #pragma unroll
            for (int i = 0; i < 2; i++) {
                int r = tr + 16 * i;
                const float* gxr = gx + ((size_t)r * TSEQ + t) * G4;
                float* gr = g_gates + r * G4;
                #pragma unroll
                for (int j2 = 0; j2 < 2; j2++) {
                    int j = jb + tc + 16 * j2;
                    float ghv = (i == 0) ? (j2 == 0 ? gh00 : gh01)
                                         : (j2 == 0 ? gh10 : gh11);
                    float gxv = gxr[j];
                    gr[j] = gxv + ghv + gxv * ghv;
                }
            }
        }
        grid_sync();

        // ---- phase B: LN + gates + cell + LN(c) + h (one block per batch row) ----
        if (bid < BATCH) {
            int r = bid;
            const float* grow = g_gates + r * G4;
            float s = 0.0f, s2 = 0.0f;
            #pragma unroll
            for (int q = 0; q < 16; q++) {
                float g = grow[tid + q * NTHR];
                s += g; s2 += g * g;
            }
            float2 tot = block_reduce2(s, s2, redA, redB);
            float mean = tot.x * (1.0f / G4);
            float var  = tot.y * (1.0f / G4) - mean * mean;
            float rstd = rsqrtf(var + 1e-5f);

            float cv[4], ov[4];
            float cs = 0.0f, cs2 = 0.0f;
            #pragma unroll
            for (int q = 0; q < 4; q++) {
                int j = tid + q * NTHR;
                float gi = (grow[j]        - mean) * rstd * lngw[j]        + lngb[j];
                float gf = (grow[j + 1024] - mean) * rstd * lngw[j + 1024] + lngb[j + 1024];
                float gg = (grow[j + 2048] - mean) * rstd * lngw[j + 2048] + lngb[j + 2048];
                float go = (grow[j + 3072] - mean) * rstd * lngw[j + 3072] + lngb[j + 3072];
                float iv = sigmoidf_(gi);
                float fv = sigmoidf_(gf);
                float gv = tanhf(gg);
                float o  = sigmoidf_(go);
                float c  = fv * g_c[r * HDIM + j] + iv * gv;
                cv[q] = c; ov[q] = o;
                cs += c; cs2 += c * c;
            }
            float2 ct = block_reduce2(cs, cs2, redA, redB);
            float cm   = ct.x * (1.0f / HDIM);
            float cvar = ct.y * (1.0f / HDIM) - cm * cm;
            float crs  = rsqrtf(cvar + 1e-5f);
            #pragma unroll
            for (int q = 0; q < 4; q++) {
                int j = tid + q * NTHR;
                float cn = (cv[q] - cm) * crs * lncw[j] + lncb[j];
                g_c[r * HDIM + j] = cn;
                float h = ov[q] * tanhf(cn);
                g_h[r * HDIM + j] = h;
                out[((size_t)r * TSEQ + t) * HDIM + j] = h;
            }
        }
        grid_sync();
    }
}

// ---------------- launch ----------------
extern "C" void kernel_launch(void* const* d_in, const int* in_sizes, int n_in,
                              void* d_out, int out_size) {
    const float* x    = (const float*)d_in[0];
    const float* W    = (const float*)d_in[1];
    const float* b    = (const float*)d_in[2];
    const float* U    = (const float*)d_in[3];
    const float* lngw = (const float*)d_in[4];
    const float* lngb = (const float*)d_in[5];
    const float* lncw = (const float*)d_in[6];
    const float* lncb = (const float*)d_in[7];
    float* y = (float*)d_out;

    float *gx, *h0;
    cudaGetSymbolAddress((void**)&gx, g_gx);
    cudaGetSymbolAddress((void**)&h0, g_h0);

    const int M = BATCH * TSEQ;   // 16384
    dim3 gg(G4 / 64, M / 64);     // (64, 256)

    // layer 0
    sgemm_tn_bias<<<gg, 256>>>(x, W, b, gx, M, G4, HDIM);
    milstm_seq<<<NBLK, NTHR>>>(gx, U, lngw, lngb, lncw, lncb, h0);
    // layer 1
    sgemm_tn_bias<<<gg, 256>>>(h0, W + (size_t)G4 * HDIM, b + G4, gx, M, G4, HDIM);
    milstm_seq<<<NBLK, NTHR>>>(gx, U + (size_t)G4 * HDIM, lngw + G4, lngb + G4,
                               lncw + HDIM, lncb + HDIM, y);
}

// round 6
// speedup vs baseline: 2.3154x; 2.3154x over previous
#include <cuda_runtime.h>
#include <cuda_fp16.h>
#include <cstdint>

#define BATCH 32
#define TSEQ  512
#define HDIM  1024
#define G4    4096
#define NBLK  128
#define NTHR  256
#define ROWP  1032                     // padded row stride in halves
#define TILEH (32 * ROWP)              // 33024 halves = 66048 B
#define SMEM_DYN (2 * TILEH * 2)       // 132096 B: hi tile + lo tile

// ---------------- scratch (device globals; no allocation allowed) ----------------
__device__ float g_gx[(size_t)BATCH * TSEQ * G4];    // 256 MB
__device__ float g_h0[(size_t)BATCH * TSEQ * HDIM];  // 64 MB
__device__ float g_gh[BATCH * G4];                   // gh result, [r][j]
__device__ float g_c[BATCH * HDIM];
__device__ __half g_hh[BATCH * HDIM];                // h state fp16 hi
__device__ __half g_hl[BATCH * HDIM];                // h state fp16 lo
__device__ __half g_Uh[2ULL * G4 * HDIM];            // U fp16 hi, 16.8 MB
__device__ __half g_Ul[2ULL * G4 * HDIM];            // U fp16 lo, 16.8 MB
__device__ unsigned g_barcnt = 0;
__device__ volatile unsigned g_bargen = 0;

// ---------------- helpers ----------------
__device__ __forceinline__ void ffma2(unsigned long long& d, unsigned long long a,
                                      unsigned long long b) {
    asm("fma.rn.f32x2 %0, %1, %2, %0;" : "+l"(d) : "l"(a), "l"(b));
}
__device__ __forceinline__ float f2sum(unsigned long long v) {
    float lo, hi;
    asm("mov.b64 {%0, %1}, %2;" : "=f"(lo), "=f"(hi) : "l"(v));
    return lo + hi;
}
__device__ __forceinline__ float sigmoidf_(float x) {
    return 1.0f / (1.0f + __expf(-x));
}
__device__ __forceinline__ uint32_t smem_u32(const void* p) {
    uint32_t a;
    asm("{ .reg .u64 t; cvta.to.shared.u64 t, %1; cvt.u32.u64 %0, t; }" : "=r"(a) : "l"(p));
    return a;
}
__device__ __forceinline__ void ldmx4(uint32_t* r, uint32_t addr) {
    asm volatile("ldmatrix.sync.aligned.m8n8.x4.shared.b16 {%0,%1,%2,%3}, [%4];"
                 : "=r"(r[0]), "=r"(r[1]), "=r"(r[2]), "=r"(r[3]) : "r"(addr));
}
__device__ __forceinline__ void mma16816(float* c, const uint32_t* a,
                                         uint32_t b0, uint32_t b1) {
    asm volatile(
        "mma.sync.aligned.m16n8k16.row.col.f32.f16.f16.f32 "
        "{%0,%1,%2,%3}, {%4,%5,%6,%7}, {%8,%9}, {%0,%1,%2,%3};"
        : "+f"(c[0]), "+f"(c[1]), "+f"(c[2]), "+f"(c[3])
        : "r"(a[0]), "r"(a[1]), "r"(a[2]), "r"(a[3]), "r"(b0), "r"(b1));
}

// grid-wide barrier; all NBLK blocks co-resident (1 block/SM by smem usage)
__device__ __forceinline__ void grid_sync() {
    __threadfence();
    __syncthreads();
    if (threadIdx.x == 0) {
        unsigned gen = g_bargen;
        if (atomicAdd(&g_barcnt, 1u) == NBLK - 1u) {
            g_barcnt = 0u;
            __threadfence();
            g_bargen = gen + 1u;
        } else {
            while (g_bargen == gen) { }
            __threadfence();
        }
    }
    __syncthreads();
}

// block-wide 2-value sum reduce
__device__ __forceinline__ float2 reduce2(float a, float b) {
    __shared__ float sA[8], sB[8];
    __syncthreads();
    #pragma unroll
    for (int o = 16; o > 0; o >>= 1) {
        a += __shfl_xor_sync(0xFFFFFFFFu, a, o);
        b += __shfl_xor_sync(0xFFFFFFFFu, b, o);
    }
    int wid = threadIdx.x >> 5, lid = threadIdx.x & 31;
    if (lid == 0) { sA[wid] = a; sB[wid] = b; }
    __syncthreads();
    if (threadIdx.x < 32) {
        a = (lid < 8) ? sA[lid] : 0.0f;
        b = (lid < 8) ? sB[lid] : 0.0f;
        #pragma unroll
        for (int o = 4; o > 0; o >>= 1) {
            a += __shfl_xor_sync(0xFFFFFFFFu, a, o);
            b += __shfl_xor_sync(0xFFFFFFFFu, b, o);
        }
        if (lid == 0) { sA[0] = a; sB[0] = b; }
    }
    __syncthreads();
    return make_float2(sA[0], sB[0]);
}

// ---------------- prep: convert U to fp16 hi/lo ----------------
__global__ void pack_U_fp16(const float* __restrict__ U) {
    size_t total = 2ULL * G4 * HDIM;
    for (size_t i = (size_t)blockIdx.x * blockDim.x + threadIdx.x; i < total;
         i += (size_t)gridDim.x * blockDim.x) {
        float v = U[i];
        __half hi = __float2half_rn(v);
        g_Uh[i] = hi;
        g_Ul[i] = __float2half_rn(v - __half2float(hi));
    }
}

// ---------------- big parallel GEMM: C = A @ B^T + bias (validated R1) ----------------
__global__ void __launch_bounds__(256) sgemm_tn_bias(
    const float* __restrict__ A, const float* __restrict__ Bm,
    const float* __restrict__ bias, float* __restrict__ C,
    int M, int N, int K)
{
    __shared__ float2 As2[8][65];
    __shared__ float2 Bs2[8][65];

    int tid = threadIdx.x;
    int n0 = blockIdx.x * 64;
    int m0 = blockIdx.y * 64;
    int tx = tid & 15;
    int ty = tid >> 4;

    unsigned long long acc[4][4] = {};

    int la_m = tid >> 2;
    int la_k = (tid & 3) * 4;
    const float* Aptr = A + (size_t)(m0 + la_m) * K + la_k;
    const float* Bptr = Bm + (size_t)(n0 + la_m) * K + la_k;
    int kq = tid & 3;

    for (int k0 = 0; k0 < K; k0 += 16) {
        float4 av = *reinterpret_cast<const float4*>(Aptr + k0);
        float4 bv = *reinterpret_cast<const float4*>(Bptr + k0);
        As2[2 * kq][la_m]     = make_float2(av.x, av.y);
        As2[2 * kq + 1][la_m] = make_float2(av.z, av.w);
        Bs2[2 * kq][la_m]     = make_float2(bv.x, bv.y);
        Bs2[2 * kq + 1][la_m] = make_float2(bv.z, bv.w);
        __syncthreads();
        #pragma unroll
        for (int kp = 0; kp < 8; kp++) {
            unsigned long long a2[4], b2[4];
            #pragma unroll
            for (int i = 0; i < 4; i++)
                a2[i] = *reinterpret_cast<const unsigned long long*>(&As2[kp][ty + 16 * i]);
            #pragma unroll
            for (int j = 0; j < 4; j++)
                b2[j] = *reinterpret_cast<const unsigned long long*>(&Bs2[kp][tx + 16 * j]);
            #pragma unroll
            for (int i = 0; i < 4; i++)
                #pragma unroll
                for (int j = 0; j < 4; j++)
                    ffma2(acc[i][j], a2[i], b2[j]);
        }
        __syncthreads();
    }

    #pragma unroll
    for (int i = 0; i < 4; i++) {
        int m = m0 + ty + 16 * i;
        #pragma unroll
        for (int j = 0; j < 4; j++) {
            int n = n0 + tx + 16 * j;
            C[(size_t)m * N + n] = f2sum(acc[i][j]) + bias[n];
        }
    }
}

// ---------------- persistent HMMA recurrent kernel (hi/lo split) ----------------
// 128 blocks, block b owns gate rows j in [32b, 32b+32).
// Warp layout: wid -> (mt = wid&1 [16 j-rows], ks = wid>>1 [256-wide K slice]).
// U hi+lo A-fragments live in registers (128 regs/lane, loaded once).
// Per step: stage h hi+lo in smem -> 3-pass mma -> cross-warp K reduce ->
// g_gh -> grid barrier -> phase B (blocks 0..31, one batch row each).
__global__ void __launch_bounds__(NTHR, 1) milstm_mma(
    const float* __restrict__ gx,
    const __half* __restrict__ Uh, const __half* __restrict__ Ul,
    const float* __restrict__ lngw, const float* __restrict__ lngb,
    const float* __restrict__ lncw, const float* __restrict__ lncb,
    float* __restrict__ out)
{
    extern __shared__ __half hs[];          // [hi tile | lo tile], each 32 x 1032 halves
    uint32_t sbase = smem_u32(hs);
    uint32_t* hs32h = reinterpret_cast<uint32_t*>(hs);           // hi, row stride 516 u32
    uint32_t* hs32l = reinterpret_cast<uint32_t*>(hs + TILEH);   // lo
    float* stg = reinterpret_cast<float*>(hs);                   // reused for reduction

    const int tid = threadIdx.x, bid = blockIdx.x;
    const int wid = tid >> 5, lane = tid & 31;
    const int mt = wid & 1, ks = wid >> 1;
    const int jb = bid * 32;

    // ---- stage U slice (hi+lo) into smem once: 32 rows x 128 uint4 each ----
    #pragma unroll
    for (int i = 0; i < 16; i++) {
        int e = tid + i * NTHR;             // 0..4095 uint4 units
        int row = e >> 7, c16 = e & 127;
        *reinterpret_cast<uint4*>(&hs[row * ROWP + c16 * 8]) =
            *reinterpret_cast<const uint4*>(Uh + (size_t)(jb + row) * HDIM + c16 * 8);
        *reinterpret_cast<uint4*>(&hs[TILEH + row * ROWP + c16 * 8]) =
            *reinterpret_cast<const uint4*>(Ul + (size_t)(jb + row) * HDIM + c16 * 8);
    }
    __syncthreads();

    // ---- preload A fragments (U hi+lo) into registers via ldmatrix ----
    uint32_t afrh[16][4], afrl[16][4];
    {
        int rowoff = mt * 16 + (lane & 7) + ((lane >> 3) & 1) * 8;
        int coloff = (lane >> 4) << 3;
        #pragma unroll
        for (int kq = 0; kq < 16; kq++) {
            int k0 = ks * 256 + kq * 16;
            uint32_t addr = sbase + (uint32_t)(rowoff * ROWP + k0 + coloff) * 2u;
            ldmx4(afrh[kq], addr);
            ldmx4(afrl[kq], addr + TILEH * 2u);
        }
    }
    __syncthreads();

    // ---- zero-init recurrent state ----
    {
        int i = bid * NTHR + tid;           // 0..32767 == BATCH*HDIM
        g_c[i] = 0.0f;
        g_hh[i] = __float2half(0.0f);
        g_hl[i] = __float2half(0.0f);
    }
    grid_sync();

    // phase-B per-thread constants
    const int j4 = tid * 4;
    float4 lwi = *(const float4*)(lngw + j4);
    float4 lwf = *(const float4*)(lngw + 1024 + j4);
    float4 lwg = *(const float4*)(lngw + 2048 + j4);
    float4 lwo = *(const float4*)(lngw + 3072 + j4);
    float4 lbi = *(const float4*)(lngb + j4);
    float4 lbf = *(const float4*)(lngb + 1024 + j4);
    float4 lbg = *(const float4*)(lngb + 2048 + j4);
    float4 lbo = *(const float4*)(lngb + 3072 + j4);
    float4 cw  = *(const float4*)(lncw + j4);
    float4 cb  = *(const float4*)(lncb + j4);

    // reduction mapping (phase A epilogue): thread -> (r, j0..j0+3)
    const int rr_ = tid >> 3;               // batch row 0..31
    const int j0_ = (tid & 7) * 4;          // j within block tile

    for (int t = 0; t < TSEQ; ++t) {
        // ---- stage h hi+lo into smem: 32 rows x 128 uint4 each ----
        #pragma unroll
        for (int i = 0; i < 16; i++) {
            int e = tid + i * NTHR;
            int row = e >> 7, c16 = e & 127;
            *reinterpret_cast<uint4*>(&hs[row * ROWP + c16 * 8]) =
                *reinterpret_cast<const uint4*>(g_hh + row * HDIM + c16 * 8);
            *reinterpret_cast<uint4*>(&hs[TILEH + row * ROWP + c16 * 8]) =
                *reinterpret_cast<const uint4*>(g_hl + row * HDIM + c16 * 8);
        }
        __syncthreads();

        // ---- 3-pass mma over this warp's 256-wide K slice ----
        float acc[4][4] = {};
        {
            int cu0 = ((ks * 256) >> 1) + (lane & 3);
            int g = lane >> 2;
            #pragma unroll
            for (int kq = 0; kq < 16; kq++) {
                int cu = cu0 + kq * 8;
                #pragma unroll
                for (int nt = 0; nt < 4; nt++) {
                    int r = nt * 8 + g;
                    uint32_t bh0 = hs32h[r * 516 + cu];
                    uint32_t bh1 = hs32h[r * 516 + cu + 4];
                    uint32_t bl0 = hs32l[r * 516 + cu];
                    uint32_t bl1 = hs32l[r * 516 + cu + 4];
                    mma16816(acc[nt], afrh[kq], bh0, bh1);   // Uhi * hhi
                    mma16816(acc[nt], afrh[kq], bl0, bl1);   // Uhi * hlo
                    mma16816(acc[nt], afrl[kq], bh0, bh1);   // Ulo * hhi
                }
            }
        }
        __syncthreads();   // done reading hs; reuse as staging

        // ---- cross-warp K reduction ----
        #pragma unroll
        for (int nt = 0; nt < 4; nt++)
            *reinterpret_cast<float4*>(&stg[((wid * 4 + nt) << 7) + (lane << 2)]) =
                *reinterpret_cast<const float4*>(acc[nt]);
        __syncthreads();
        {
            int r = rr_;
            int ntv = r >> 3, rrv = r & 7;
            float4 o;
            float* po = &o.x;
            #pragma unroll
            for (int q = 0; q < 4; q++) {
                int j = j0_ + q;
                int mtv = j >> 4, jj = j & 15;
                int lidx = ((jj & 7) << 2) + (rrv >> 1);
                int reg = ((jj >> 3) << 1) + (rrv & 1);
                float s = 0.0f;
                #pragma unroll
                for (int kk = 0; kk < 4; kk++)
                    s += stg[(((kk * 2 + mtv) * 4 + ntv) << 7) + (lidx << 2) + reg];
                po[q] = s;
            }
            *reinterpret_cast<float4*>(&g_gh[r * G4 + jb + j0_]) = o;
        }
        grid_sync();

        // ---- phase B: blocks 0..31, one batch row each ----
        if (bid < BATCH) {
            int r = bid;
            const float* ghr = g_gh + r * G4;
            const float* gxr = gx + ((size_t)r * TSEQ + t) * G4;
            float4 hi = *(const float4*)(ghr + j4);
            float4 hf = *(const float4*)(ghr + 1024 + j4);
            float4 hg = *(const float4*)(ghr + 2048 + j4);
            float4 ho = *(const float4*)(ghr + 3072 + j4);
            float4 xi = *(const float4*)(gxr + j4);
            float4 xf = *(const float4*)(gxr + 1024 + j4);
            float4 xg = *(const float4*)(gxr + 2048 + j4);
            float4 xo = *(const float4*)(gxr + 3072 + j4);
            float vi[4], vf[4], vg[4], vo[4];
            const float* phi = &hi.x; const float* pxi = &xi.x;
            const float* phf = &hf.x; const float* pxf = &xf.x;
            const float* phg = &hg.x; const float* pxg = &xg.x;
            const float* pho = &ho.x; const float* pxo = &xo.x;
            float s = 0.0f, s2 = 0.0f;
            #pragma unroll
            for (int q = 0; q < 4; q++) {
                vi[q] = pxi[q] + phi[q] + pxi[q] * phi[q];
                vf[q] = pxf[q] + phf[q] + pxf[q] * phf[q];
                vg[q] = pxg[q] + phg[q] + pxg[q] * phg[q];
                vo[q] = pxo[q] + pho[q] + pxo[q] * pho[q];
                s  += vi[q] + vf[q] + vg[q] + vo[q];
                s2 += vi[q]*vi[q] + vf[q]*vf[q] + vg[q]*vg[q] + vo[q]*vo[q];
            }
            float2 tot = reduce2(s, s2);
            float mean = tot.x * (1.0f / G4);
            float var  = tot.y * (1.0f / G4) - mean * mean;
            float rstd = rsqrtf(var + 1e-5f);

            float4 cprev = *(const float4*)(g_c + r * HDIM + j4);
            const float* pcp = &cprev.x;
            const float* pwi = &lwi.x; const float* pwf = &lwf.x;
            const float* pwg = &lwg.x; const float* pwo = &lwo.x;
            const float* pbi = &lbi.x; const float* pbf = &lbf.x;
            const float* pbg = &lbg.x; const float* pbo = &lbo.x;
            float ov[4], cv[4];
            float cs = 0.0f, cs2 = 0.0f;
            #pragma unroll
            for (int q = 0; q < 4; q++) {
                float gi = (vi[q] - mean) * rstd * pwi[q] + pbi[q];
                float gf = (vf[q] - mean) * rstd * pwf[q] + pbf[q];
                float gg = (vg[q] - mean) * rstd * pwg[q] + pbg[q];
                float go = (vo[q] - mean) * rstd * pwo[q] + pbo[q];
                float ivv = sigmoidf_(gi);
                float fvv = sigmoidf_(gf);
                float gvv = tanhf(gg);
                ov[q] = sigmoidf_(go);
                float c = fvv * pcp[q] + ivv * gvv;
                cv[q] = c;
                cs += c; cs2 += c * c;
            }
            float2 ct = reduce2(cs, cs2);
            float cm   = ct.x * (1.0f / HDIM);
            float cvar = ct.y * (1.0f / HDIM) - cm * cm;
            float crs  = rsqrtf(cvar + 1e-5f);
            const float* pcw = &cw.x; const float* pcb = &cb.x;
            float4 cno, hno;
            float* pcn = &cno.x; float* phn = &hno.x;
            #pragma unroll
            for (int q = 0; q < 4; q++) {
                float cn = (cv[q] - cm) * crs * pcw[q] + pcb[q];
                pcn[q] = cn;
                phn[q] = ov[q] * tanhf(cn);
            }
            *(float4*)(g_c + r * HDIM + j4) = cno;
            *(float4*)(out + ((size_t)r * TSEQ + t) * HDIM + j4) = hno;
            // split h into fp16 hi/lo for the next step's MMA
            __half hh0 = __float2half_rn(hno.x);
            __half hh1 = __float2half_rn(hno.y);
            __half hh2 = __float2half_rn(hno.z);
            __half hh3 = __float2half_rn(hno.w);
            __half hl0 = __float2half_rn(hno.x - __half2float(hh0));
            __half hl1 = __float2half_rn(hno.y - __half2float(hh1));
            __half hl2 = __float2half_rn(hno.z - __half2float(hh2));
            __half hl3 = __float2half_rn(hno.w - __half2float(hh3));
            *reinterpret_cast<__half2*>(g_hh + r * HDIM + j4)     = __halves2half2(hh0, hh1);
            *reinterpret_cast<__half2*>(g_hh + r * HDIM + j4 + 2) = __halves2half2(hh2, hh3);
            *reinterpret_cast<__half2*>(g_hl + r * HDIM + j4)     = __halves2half2(hl0, hl1);
            *reinterpret_cast<__half2*>(g_hl + r * HDIM + j4 + 2) = __halves2half2(hl2, hl3);
        }
        grid_sync();
    }
}

// ---------------- launch ----------------
extern "C" void kernel_launch(void* const* d_in, const int* in_sizes, int n_in,
                              void* d_out, int out_size) {
    const float* x    = (const float*)d_in[0];
    const float* W    = (const float*)d_in[1];
    const float* b    = (const float*)d_in[2];
    const float* U    = (const float*)d_in[3];
    const float* lngw = (const float*)d_in[4];
    const float* lngb = (const float*)d_in[5];
    const float* lncw = (const float*)d_in[6];
    const float* lncb = (const float*)d_in[7];
    float* y = (float*)d_out;

    cudaFuncSetAttribute(milstm_mma, cudaFuncAttributeMaxDynamicSharedMemorySize,
                         SMEM_DYN);

    float *gx, *h0;
    cudaGetSymbolAddress((void**)&gx, g_gx);
    cudaGetSymbolAddress((void**)&h0, g_h0);
    __half *Uh, *Ul;
    cudaGetSymbolAddress((void**)&Uh, g_Uh);
    cudaGetSymbolAddress((void**)&Ul, g_Ul);

    const int M = BATCH * TSEQ;
    dim3 gg(G4 / 64, M / 64);

    pack_U_fp16<<<2048, 256>>>(U);
    // layer 0
    sgemm_tn_bias<<<gg, 256>>>(x, W, b, gx, M, G4, HDIM);
    milstm_mma<<<NBLK, NTHR, SMEM_DYN>>>(gx, Uh, Ul, lngw, lngb, lncw, lncb, h0);
    // layer 1
    sgemm_tn_bias<<<gg, 256>>>(h0, W + (size_t)G4 * HDIM, b + G4, gx, M, G4, HDIM);
    milstm_mma<<<NBLK, NTHR, SMEM_DYN>>>(gx, Uh + (size_t)G4 * HDIM,
                                         Ul + (size_t)G4 * HDIM,
                                         lngw + G4, lngb + G4,
                                         lncw + HDIM, lncb + HDIM, y);
}

// round 10
// speedup vs baseline: 3.2567x; 1.4065x over previous
#include <cuda_runtime.h>
#include <cuda_fp16.h>
#include <cstdint>

#define BATCH 32
#define TSEQ  512
#define HDIM  1024
#define G4    4096
#define NBLK  128
#define NTHR  256
#define SMEM_DYN  135168      // milstm: U-stage 2x(128x264x2B)
#define SMEM_GEMM 73728       // sgemm: 4 tiles of 128x72 halves

// ---------------- scratch (device globals; no allocation allowed) ----------------
__device__ float g_gx[(size_t)BATCH * TSEQ * G4];    // 256 MB
__device__ float g_h0[(size_t)BATCH * TSEQ * HDIM];  // 64 MB
__device__ float g_ghp[4ULL * BATCH * G4];           // K-split partials, [ks][r][j]
__device__ float g_c[BATCH * HDIM];
__device__ __half g_hh[BATCH * HDIM];                // h state fp16 hi
__device__ __half g_hl[BATCH * HDIM];                // h state fp16 lo
__device__ __half g_Uh[2ULL * G4 * HDIM];            // U fp16 hi
__device__ __half g_Ul[2ULL * G4 * HDIM];            // U fp16 lo
__device__ __half g_Wh[2ULL * G4 * HDIM];            // W fp16 hi
__device__ __half g_Wl[2ULL * G4 * HDIM];            // W fp16 lo
__device__ __half g_Ah[(size_t)BATCH * TSEQ * HDIM]; // GEMM A fp16 hi (x or h0)
__device__ __half g_Al[(size_t)BATCH * TSEQ * HDIM]; // GEMM A fp16 lo
__device__ unsigned g_barcnt = 0;
__device__ volatile unsigned g_bargen = 0;

// ---------------- helpers ----------------
__device__ __forceinline__ float sigmoidf_(float x) {
    return 1.0f / (1.0f + __expf(-x));
}
__device__ __forceinline__ uint32_t smem_u32(const void* p) {
    uint32_t a;
    asm("{ .reg .u64 t; cvta.to.shared.u64 t, %1; cvt.u32.u64 %0, t; }" : "=r"(a) : "l"(p));
    return a;
}
__device__ __forceinline__ void ldmx4(uint32_t* r, uint32_t addr) {
    asm volatile("ldmatrix.sync.aligned.m8n8.x4.shared.b16 {%0,%1,%2,%3}, [%4];"
                 : "=r"(r[0]), "=r"(r[1]), "=r"(r[2]), "=r"(r[3]) : "r"(addr));
}
__device__ __forceinline__ void mma16816(float* c, const uint32_t* a,
                                         uint32_t b0, uint32_t b1) {
    asm volatile(
        "mma.sync.aligned.m16n8k16.row.col.f32.f16.f16.f32 "
        "{%0,%1,%2,%3}, {%4,%5,%6,%7}, {%8,%9}, {%0,%1,%2,%3};"
        : "+f"(c[0]), "+f"(c[1]), "+f"(c[2]), "+f"(c[3])
        : "r"(a[0]), "r"(a[1]), "r"(a[2]), "r"(a[3]), "r"(b0), "r"(b1));
}
__device__ __forceinline__ void cp16(uint32_t dst, const void* src) {
    asm volatile("cp.async.cg.shared.global [%0], [%1], 16;" :: "r"(dst), "l"(src));
}
__device__ __forceinline__ void cp_commit() {
    asm volatile("cp.async.commit_group;" ::: "memory");
}
__device__ __forceinline__ void cp_wait0() {
    asm volatile("cp.async.wait_group 0;" ::: "memory");
}

// grid-wide barrier; all NBLK blocks co-resident (1 block/SM by smem usage)
__device__ __forceinline__ void grid_sync() {
    __threadfence();
    __syncthreads();
    if (threadIdx.x == 0) {
        unsigned gen = g_bargen;
        if (atomicAdd(&g_barcnt, 1u) == NBLK - 1u) {
            g_barcnt = 0u;
            __threadfence();
            g_bargen = gen + 1u;
        } else {
            while (g_bargen == gen) { }
            __threadfence();
        }
    }
    __syncthreads();
}

// block-wide 2-value sum reduce
__device__ __forceinline__ float2 reduce2(float a, float b) {
    __shared__ float sA[8], sB[8];
    __syncthreads();
    #pragma unroll
    for (int o = 16; o > 0; o >>= 1) {
        a += __shfl_xor_sync(0xFFFFFFFFu, a, o);
        b += __shfl_xor_sync(0xFFFFFFFFu, b, o);
    }
    int wid = threadIdx.x >> 5, lid = threadIdx.x & 31;
    if (lid == 0) { sA[wid] = a; sB[wid] = b; }
    __syncthreads();
    if (threadIdx.x < 32) {
        a = (lid < 8) ? sA[lid] : 0.0f;
        b = (lid < 8) ? sB[lid] : 0.0f;
        #pragma unroll
        for (int o = 4; o > 0; o >>= 1) {
            a += __shfl_xor_sync(0xFFFFFFFFu, a, o);
            b += __shfl_xor_sync(0xFFFFFFFFu, b, o);
        }
        if (lid == 0) { sA[0] = a; sB[0] = b; }
    }
    __syncthreads();
    return make_float2(sA[0], sB[0]);
}

// ---------------- pack kernels: fp32 -> fp16 hi/lo ----------------
__global__ void pack_hilo(const float* __restrict__ src, __half* __restrict__ dh,
                          __half* __restrict__ dl, size_t total) {
    for (size_t i = (size_t)blockIdx.x * blockDim.x + threadIdx.x; i < total;
         i += (size_t)gridDim.x * blockDim.x) {
        float v = src[i];
        __half hi = __float2half_rn(v);
        dh[i] = hi;
        dl[i] = __float2half_rn(v - __half2float(hi));
    }
}

// ---------------- HMMA big GEMM: C[16384,4096] = A @ B^T + bias ----------------
// 3-pass fp16 hi/lo. Tiles 128(m) x 128(n), BK=64, 256 threads, 2 blocks/SM.
__global__ void __launch_bounds__(256, 2) sgemm_hmma(
    const __half* __restrict__ Ah, const __half* __restrict__ Al,
    const __half* __restrict__ Bh, const __half* __restrict__ Bl,
    const float* __restrict__ bias, float* __restrict__ C)
{
    extern __shared__ __half sm[];
    __half* sAh = sm;                // 128 x 72 halves
    __half* sAl = sm + 9216;
    __half* sBh = sm + 18432;
    __half* sBl = sm + 27648;
    uint32_t base = smem_u32(sm);
    uint32_t* sBh32 = reinterpret_cast<uint32_t*>(sBh);
    uint32_t* sBl32 = reinterpret_cast<uint32_t*>(sBl);

    const int tid = threadIdx.x, wid = tid >> 5, lane = tid & 31;
    const int n0 = blockIdx.x * 128, m0 = blockIdx.y * 128;

    float acc[16][4] = {};

    const int rowoff = wid * 16 + (lane & 7) + ((lane >> 3) & 1) * 8;
    const int coloff = (lane >> 4) << 3;
    const int g = lane >> 2;

    for (int k0 = 0; k0 < HDIM; k0 += 64) {
        __syncthreads();
        #pragma unroll
        for (int i = 0; i < 4; i++) {
            int e = tid + i * 256;              // 0..1023
            int row = e >> 3, c8 = (e & 7) * 8;
            *reinterpret_cast<uint4*>(&sAh[row * 72 + c8]) =
                *reinterpret_cast<const uint4*>(&Ah[(size_t)(m0 + row) * HDIM + k0 + c8]);
            *reinterpret_cast<uint4*>(&sAl[row * 72 + c8]) =
                *reinterpret_cast<const uint4*>(&Al[(size_t)(m0 + row) * HDIM + k0 + c8]);
            *reinterpret_cast<uint4*>(&sBh[row * 72 + c8]) =
                *reinterpret_cast<const uint4*>(&Bh[(size_t)(n0 + row) * HDIM + k0 + c8]);
            *reinterpret_cast<uint4*>(&sBl[row * 72 + c8]) =
                *reinterpret_cast<const uint4*>(&Bl[(size_t)(n0 + row) * HDIM + k0 + c8]);
        }
        __syncthreads();
        #pragma unroll
        for (int kq = 0; kq < 4; kq++) {
            uint32_t ah[4], al[4];
            uint32_t addr = base + (uint32_t)(rowoff * 72 + kq * 16 + coloff) * 2u;
            ldmx4(ah, addr);
            ldmx4(al, addr + 18432u);
            const int cu = kq * 8 + (lane & 3);
            #pragma unroll
            for (int nt = 0; nt < 16; nt++) {
                int r = nt * 8 + g;
                uint32_t bh0 = sBh32[r * 36 + cu], bh1 = sBh32[r * 36 + cu + 4];
                uint32_t bl0 = sBl32[r * 36 + cu], bl1 = sBl32[r * 36 + cu + 4];
                mma16816(acc[nt], ah, bh0, bh1);
                mma16816(acc[nt], ah, bl0, bl1);
                mma16816(acc[nt], al, bh0, bh1);
            }
        }
    }

    #pragma unroll
    for (int nt = 0; nt < 16; nt++)
        #pragma unroll
        for (int c = 0; c < 4; c++) {
            int m = m0 + wid * 16 + ((c >> 1) << 3) + (lane >> 2);
            int n = n0 + nt * 8 + ((lane & 3) << 1) + (c & 1);
            C[(size_t)m * G4 + n] = acc[nt][c] + __ldg(bias + n);
        }
}

// ---------------- persistent HMMA recurrent kernel (K-split) ----------------
// 128 blocks: bid -> (jt = bid&31, ks4 = bid>>5). Block owns j [jt*128,+128),
// K [ks4*256,+256). Warp wid owns 16 j rows, full block-K (kq 0..15).
// Per step: cp.async gx prefetch (bid<32) -> stage h slice -> 3-pass MMA ->
// store partials g_ghp[ks4][r][j] -> barrier -> phase B sums 4 partials.
__global__ void __launch_bounds__(NTHR, 1) milstm_mma(
    const float* __restrict__ gx,
    const __half* __restrict__ Uh, const __half* __restrict__ Ul,
    const float* __restrict__ lngw, const float* __restrict__ lngb,
    const float* __restrict__ lncw, const float* __restrict__ lncb,
    float* __restrict__ out)
{
    extern __shared__ char dsm[];
    uint32_t sbase = smem_u32(dsm);
    __half* hsm = reinterpret_cast<__half*>(dsm);
    uint32_t* hs32h = reinterpret_cast<uint32_t*>(dsm);            // h hi: 32 x 264 halves
    uint32_t* hs32l = reinterpret_cast<uint32_t*>(dsm + 16896);    // h lo
    float* sgx = reinterpret_cast<float*>(dsm + 33792);            // 4096 floats

    const int tid = threadIdx.x, bid = blockIdx.x;
    const int wid = tid >> 5, lane = tid & 31;
    const int jt = bid & 31, ks4 = bid >> 5;
    const int jb = jt * 128, kb = ks4 * 256;

    // ---- stage U slice (128 rows x 256 K, hi+lo) into smem once ----
    #pragma unroll
    for (int i = 0; i < 16; i++) {
        int e = tid + i * NTHR;                 // 0..4095 uint4
        int row = e >> 5, c8 = (e & 31) * 8;
        *reinterpret_cast<uint4*>(&hsm[row * 264 + c8]) =
            *reinterpret_cast<const uint4*>(&Uh[(size_t)(jb + row) * HDIM + kb + c8]);
        *reinterpret_cast<uint4*>(&hsm[33792 + row * 264 + c8]) =
            *reinterpret_cast<const uint4*>(&Ul[(size_t)(jb + row) * HDIM + kb + c8]);
    }
    __syncthreads();

    // ---- preload U A-fragments (hi+lo) ----
    uint32_t afrh[16][4], afrl[16][4];
    {
        int rowoff = wid * 16 + (lane & 7) + ((lane >> 3) & 1) * 8;
        int coloff = (lane >> 4) << 3;
        #pragma unroll
        for (int kq = 0; kq < 16; kq++) {
            uint32_t addr = sbase + (uint32_t)(rowoff * 264 + kq * 16 + coloff) * 2u;
            ldmx4(afrh[kq], addr);
            ldmx4(afrl[kq], addr + 67584u);
        }
    }
    __syncthreads();

    // ---- zero-init recurrent state ----
    {
        int i = bid * NTHR + tid;               // covers 32768 = BATCH*HDIM
        g_c[i] = 0.0f;
        g_hh[i] = __float2half(0.0f);
        g_hl[i] = __float2half(0.0f);
    }
    grid_sync();

    // phase-B per-thread constants
    const int j4 = tid * 4;
    float4 lw[4], lb[4];
    #pragma unroll
    for (int s = 0; s < 4; s++) {
        lw[s] = *(const float4*)(lngw + s * 1024 + j4);
        lb[s] = *(const float4*)(lngb + s * 1024 + j4);
    }
    float4 cw = *(const float4*)(lncw + j4);
    float4 cb = *(const float4*)(lncb + j4);

    const int g = lane >> 2;
    const int cu0 = lane & 3;

    for (int t = 0; t < TSEQ; ++t) {
        // ---- gx prefetch for phase B (own slice only; self-consumed) ----
        if (bid < BATCH) {
            const char* src = (const char*)(gx + ((size_t)bid * TSEQ + t) * G4);
            #pragma unroll
            for (int i = 0; i < 4; i++)
                cp16(sbase + 33792u + (uint32_t)(tid * 16 + i * 4096),
                     src + tid * 16 + i * 4096);
            cp_commit();
        }

        // ---- stage h slice (32 r x 256 K, hi+lo) ----
        #pragma unroll
        for (int i = 0; i < 4; i++) {
            int e = tid + i * NTHR;             // 0..1023 uint4
            int row = e >> 5, c8 = (e & 31) * 8;
            *reinterpret_cast<uint4*>(&hsm[row * 264 + c8]) =
                *reinterpret_cast<const uint4*>(&g_hh[row * HDIM + kb + c8]);
            *reinterpret_cast<uint4*>(&hsm[8448 + row * 264 + c8]) =
                *reinterpret_cast<const uint4*>(&g_hl[row * HDIM + kb + c8]);
        }
        __syncthreads();

        // ---- 3-pass MMA over block-K slice ----
        float acc[4][4] = {};
        #pragma unroll
        for (int kq = 0; kq < 16; kq++) {
            int cu = kq * 8 + cu0;
            #pragma unroll
            for (int nt = 0; nt < 4; nt++) {
                int r = nt * 8 + g;
                uint32_t bh0 = hs32h[r * 132 + cu], bh1 = hs32h[r * 132 + cu + 4];
                uint32_t bl0 = hs32l[r * 132 + cu], bl1 = hs32l[r * 132 + cu + 4];
                mma16816(acc[nt], afrh[kq], bh0, bh1);
                mma16816(acc[nt], afrh[kq], bl0, bl1);
                mma16816(acc[nt], afrl[kq], bh0, bh1);
            }
        }
        __syncthreads();   // hs reads done before next-step overwrite

        // ---- store partials directly: g_ghp[ks4][r][j] ----
        #pragma unroll
        for (int nt = 0; nt < 4; nt++)
            #pragma unroll
            for (int c = 0; c < 4; c++) {
                int jl = wid * 16 + ((c >> 1) << 3) + (lane >> 2);
                int r = nt * 8 + ((lane & 3) << 1) + (c & 1);
                g_ghp[(size_t)(ks4 * 32 + r) * G4 + jb + jl] = acc[nt][c];
            }
        grid_sync();

        // ---- phase B: blocks 0..31, one batch row each ----
        if (bid < BATCH) {
            cp_wait0();
            const int r = bid;
            float v[4][4];
            float s = 0.0f, s2 = 0.0f;
            #pragma unroll
            for (int sec = 0; sec < 4; sec++) {
                size_t off = (size_t)r * G4 + sec * 1024 + j4;
                float4 a0 = *(const float4*)&g_ghp[off];
                float4 a1 = *(const float4*)&g_ghp[off + 32ULL * G4];
                float4 a2 = *(const float4*)&g_ghp[off + 64ULL * G4];
                float4 a3 = *(const float4*)&g_ghp[off + 96ULL * G4];
                float4 xv = *(const float4*)(sgx + sec * 1024 + j4);
                float gh0 = a0.x + a1.x + a2.x + a3.x;
                float gh1 = a0.y + a1.y + a2.y + a3.y;
                float gh2 = a0.z + a1.z + a2.z + a3.z;
                float gh3 = a0.w + a1.w + a2.w + a3.w;
                v[sec][0] = xv.x + gh0 + xv.x * gh0;
                v[sec][1] = xv.y + gh1 + xv.y * gh1;
                v[sec][2] = xv.z + gh2 + xv.z * gh2;
                v[sec][3] = xv.w + gh3 + xv.w * gh3;
                #pragma unroll
                for (int q = 0; q < 4; q++) { s += v[sec][q]; s2 += v[sec][q] * v[sec][q]; }
            }
            float2 tot = reduce2(s, s2);
            float mean = tot.x * (1.0f / G4);
            float var  = tot.y * (1.0f / G4) - mean * mean;
            float rstd = rsqrtf(var + 1e-5f);

            float4 cprev = *(const float4*)(g_c + r * HDIM + j4);
            const float* pcp = &cprev.x;
            float ov[4], cv[4];
            float cs = 0.0f, cs2 = 0.0f;
            #pragma unroll
            for (int q = 0; q < 4; q++) {
                const float* pw0 = &lw[0].x; const float* pb0 = &lb[0].x;
                const float* pw1 = &lw[1].x; const float* pb1 = &lb[1].x;
                const float* pw2 = &lw[2].x; const float* pb2 = &lb[2].x;
                const float* pw3 = &lw[3].x; const float* pb3 = &lb[3].x;
                float gi = (v[0][q] - mean) * rstd * pw0[q] + pb0[q];
                float gf = (v[1][q] - mean) * rstd * pw1[q] + pb1[q];
                float gg = (v[2][q] - mean) * rstd * pw2[q] + pb2[q];
                float go = (v[3][q] - mean) * rstd * pw3[q] + pb3[q];
                float ivv = sigmoidf_(gi);
                float fvv = sigmoidf_(gf);
                float gvv = tanhf(gg);
                ov[q] = sigmoidf_(go);
                float c = fvv * pcp[q] + ivv * gvv;
                cv[q] = c;
                cs += c; cs2 += c * c;
            }
            float2 ct = reduce2(cs, cs2);
            float cm   = ct.x * (1.0f / HDIM);
            float cvar = ct.y * (1.0f / HDIM) - cm * cm;
            float crs  = rsqrtf(cvar + 1e-5f);
            const float* pcw = &cw.x; const float* pcb = &cb.x;
            float4 cno, hno;
            float* pcn = &cno.x; float* phn = &hno.x;
            #pragma unroll
            for (int q = 0; q < 4; q++) {
                float cn = (cv[q] - cm) * crs * pcw[q] + pcb[q];
                pcn[q] = cn;
                phn[q] = ov[q] * tanhf(cn);
            }
            *(float4*)(g_c + r * HDIM + j4) = cno;
            *(float4*)(out + ((size_t)r * TSEQ + t) * HDIM + j4) = hno;
            __half hh0 = __float2half_rn(hno.x);
            __half hh1 = __float2half_rn(hno.y);
            __half hh2 = __float2half_rn(hno.z);
            __half hh3 = __float2half_rn(hno.w);
            __half hl0 = __float2half_rn(hno.x - __half2float(hh0));
            __half hl1 = __float2half_rn(hno.y - __half2float(hh1));
            __half hl2 = __float2half_rn(hno.z - __half2float(hh2));
            __half hl3 = __float2half_rn(hno.w - __half2float(hh3));
            *reinterpret_cast<__half2*>(g_hh + r * HDIM + j4)     = __halves2half2(hh0, hh1);
            *reinterpret_cast<__half2*>(g_hh + r * HDIM + j4 + 2) = __halves2half2(hh2, hh3);
            *reinterpret_cast<__half2*>(g_hl + r * HDIM + j4)     = __halves2half2(hl0, hl1);
            *reinterpret_cast<__half2*>(g_hl + r * HDIM + j4 + 2) = __halves2half2(hl2, hl3);
        }
        grid_sync();
    }
}

// ---------------- launch ----------------
extern "C" void kernel_launch(void* const* d_in, const int* in_sizes, int n_in,
                              void* d_out, int out_size) {
    const float* x    = (const float*)d_in[0];
    const float* W    = (const float*)d_in[1];
    const float* b    = (const float*)d_in[2];
    const float* U    = (const float*)d_in[3];
    const float* lngw = (const float*)d_in[4];
    const float* lngb = (const float*)d_in[5];
    const float* lncw = (const float*)d_in[6];
    const float* lncb = (const float*)d_in[7];
    float* y = (float*)d_out;

    cudaFuncSetAttribute(milstm_mma, cudaFuncAttributeMaxDynamicSharedMemorySize,
                         SMEM_DYN);
    cudaFuncSetAttribute(sgemm_hmma, cudaFuncAttributeMaxDynamicSharedMemorySize,
                         SMEM_GEMM);

    float *gx, *h0;
    cudaGetSymbolAddress((void**)&gx, g_gx);
    cudaGetSymbolAddress((void**)&h0, g_h0);
    __half *Uh, *Ul, *Wh, *Wl, *Ah, *Al;
    cudaGetSymbolAddress((void**)&Uh, g_Uh);
    cudaGetSymbolAddress((void**)&Ul, g_Ul);
    cudaGetSymbolAddress((void**)&Wh, g_Wh);
    cudaGetSymbolAddress((void**)&Wl, g_Wl);
    cudaGetSymbolAddress((void**)&Ah, g_Ah);
    cudaGetSymbolAddress((void**)&Al, g_Al);

    const size_t WSZ = 2ULL * G4 * HDIM;
    const size_t ASZ = (size_t)BATCH * TSEQ * HDIM;
    const size_t LOFF = (size_t)G4 * HDIM;

    pack_hilo<<<1024, 256>>>(U, Uh, Ul, WSZ);
    pack_hilo<<<1024, 256>>>(W, Wh, Wl, WSZ);
    pack_hilo<<<1024, 256>>>(x, Ah, Al, ASZ);

    dim3 gg(G4 / 128, BATCH * TSEQ / 128);   // (32, 128)

    // layer 0
    sgemm_hmma<<<gg, 256, SMEM_GEMM>>>(Ah, Al, Wh, Wl, b, gx);
    milstm_mma<<<NBLK, NTHR, SMEM_DYN>>>(gx, Uh, Ul, lngw, lngb, lncw, lncb, h0);
    // layer 1
    pack_hilo<<<1024, 256>>>(h0, Ah, Al, ASZ);
    sgemm_hmma<<<gg, 256, SMEM_GEMM>>>(Ah, Al, Wh + LOFF, Wl + LOFF, b + G4, gx);
    milstm_mma<<<NBLK, NTHR, SMEM_DYN>>>(gx, Uh + LOFF, Ul + LOFF,
                                         lngw + G4, lngb + G4,
                                         lncw + HDIM, lncb + HDIM, y);
}

// round 11
// speedup vs baseline: 3.4418x; 1.0568x over previous
#include <cuda_runtime.h>
#include <cuda_fp16.h>
#include <cstdint>

#define BATCH 32
#define TSEQ  512
#define HDIM  1024
#define G4    4096
#define NBLK  128
#define NTHR  256
#define SMEM_DYN  135168      // milstm: U-stage 2x(128x264x2B)
#define SMEM_GEMM 73728       // sgemm: 4 tiles of 128x72 halves

// ---------------- scratch (device globals; no allocation allowed) ----------------
__device__ float g_gx[(size_t)BATCH * TSEQ * G4];    // 256 MB
__device__ float g_h0[(size_t)BATCH * TSEQ * HDIM];  // 64 MB
__device__ float g_ghp[4ULL * BATCH * G4];           // K-split partials, [ks][r][j]
__device__ float g_c[BATCH * HDIM];
__device__ __half g_hh[BATCH * HDIM];                // h state fp16 hi
__device__ __half g_hl[BATCH * HDIM];                // h state fp16 lo
__device__ __half g_Uh[2ULL * G4 * HDIM];            // U fp16 hi
__device__ __half g_Ul[2ULL * G4 * HDIM];            // U fp16 lo
__device__ __half g_Wh[2ULL * G4 * HDIM];            // W fp16 hi
__device__ __half g_Wl[2ULL * G4 * HDIM];            // W fp16 lo
__device__ __half g_Ah[(size_t)BATCH * TSEQ * HDIM]; // GEMM A fp16 hi (x or h0)
__device__ __half g_Al[(size_t)BATCH * TSEQ * HDIM]; // GEMM A fp16 lo
__device__ unsigned g_barcnt = 0;
__device__ volatile unsigned g_bargen = 0;

// ---------------- helpers ----------------
__device__ __forceinline__ float sigmoidf_(float x) {
    return 1.0f / (1.0f + __expf(-x));
}
// fast tanh: 1 - 2/(e^{2x}+1); MUFU-based, rel err ~1e-6, saturates correctly
__device__ __forceinline__ float ftanh(float x) {
    float e = __expf(2.0f * x);
    return 1.0f - 2.0f / (e + 1.0f);
}
__device__ __forceinline__ uint32_t smem_u32(const void* p) {
    uint32_t a;
    asm("{ .reg .u64 t; cvta.to.shared.u64 t, %1; cvt.u32.u64 %0, t; }" : "=r"(a) : "l"(p));
    return a;
}
__device__ __forceinline__ void ldmx4(uint32_t* r, uint32_t addr) {
    asm volatile("ldmatrix.sync.aligned.m8n8.x4.shared.b16 {%0,%1,%2,%3}, [%4];"
                 : "=r"(r[0]), "=r"(r[1]), "=r"(r[2]), "=r"(r[3]) : "r"(addr));
}
__device__ __forceinline__ void mma16816(float* c, const uint32_t* a,
                                         uint32_t b0, uint32_t b1) {
    asm volatile(
        "mma.sync.aligned.m16n8k16.row.col.f32.f16.f16.f32 "
        "{%0,%1,%2,%3}, {%4,%5,%6,%7}, {%8,%9}, {%0,%1,%2,%3};"
        : "+f"(c[0]), "+f"(c[1]), "+f"(c[2]), "+f"(c[3])
        : "r"(a[0]), "r"(a[1]), "r"(a[2]), "r"(a[3]), "r"(b0), "r"(b1));
}
__device__ __forceinline__ void cp16(uint32_t dst, const void* src) {
    asm volatile("cp.async.cg.shared.global [%0], [%1], 16;" :: "r"(dst), "l"(src));
}
__device__ __forceinline__ void cp_commit() {
    asm volatile("cp.async.commit_group;" ::: "memory");
}
__device__ __forceinline__ void cp_wait0() {
    asm volatile("cp.async.wait_group 0;" ::: "memory");
}

// grid-wide barrier; all NBLK blocks co-resident (1 block/SM by smem usage)
__device__ __forceinline__ void grid_sync() {
    __threadfence();
    __syncthreads();
    if (threadIdx.x == 0) {
        unsigned gen = g_bargen;
        if (atomicAdd(&g_barcnt, 1u) == NBLK - 1u) {
            g_barcnt = 0u;
            __threadfence();
            g_bargen = gen + 1u;
        } else {
            while (g_bargen == gen) { }
            __threadfence();
        }
    }
    __syncthreads();
}

// block-wide 2-value sum reduce
__device__ __forceinline__ float2 reduce2(float a, float b) {
    __shared__ float sA[8], sB[8];
    __syncthreads();
    #pragma unroll
    for (int o = 16; o > 0; o >>= 1) {
        a += __shfl_xor_sync(0xFFFFFFFFu, a, o);
        b += __shfl_xor_sync(0xFFFFFFFFu, b, o);
    }
    int wid = threadIdx.x >> 5, lid = threadIdx.x & 31;
    if (lid == 0) { sA[wid] = a; sB[wid] = b; }
    __syncthreads();
    if (threadIdx.x < 32) {
        a = (lid < 8) ? sA[lid] : 0.0f;
        b = (lid < 8) ? sB[lid] : 0.0f;
        #pragma unroll
        for (int o = 4; o > 0; o >>= 1) {
            a += __shfl_xor_sync(0xFFFFFFFFu, a, o);
            b += __shfl_xor_sync(0xFFFFFFFFu, b, o);
        }
        if (lid == 0) { sA[0] = a; sB[0] = b; }
    }
    __syncthreads();
    return make_float2(sA[0], sB[0]);
}

// ---------------- pack kernels: fp32 -> fp16 hi/lo ----------------
__global__ void pack_hilo(const float* __restrict__ src, __half* __restrict__ dh,
                          __half* __restrict__ dl, size_t total) {
    for (size_t i = (size_t)blockIdx.x * blockDim.x + threadIdx.x; i < total;
         i += (size_t)gridDim.x * blockDim.x) {
        float v = src[i];
        __half hi = __float2half_rn(v);
        dh[i] = hi;
        dl[i] = __float2half_rn(v - __half2float(hi));
    }
}

// ---------------- HMMA big GEMM: C[16384,4096] = A @ B^T + bias ----------------
// 3-pass fp16 hi/lo. Tiles 128(m) x 128(n), BK=64, 256 threads, 2 blocks/SM.
// B fragments loaded with ldmatrix.x4 (2 nt tiles per op), conflict-free
// (row stride 144 B = 36 words = 4 mod 32).
__global__ void __launch_bounds__(256, 2) sgemm_hmma(
    const __half* __restrict__ Ah, const __half* __restrict__ Al,
    const __half* __restrict__ Bh, const __half* __restrict__ Bl,
    const float* __restrict__ bias, float* __restrict__ C)
{
    extern __shared__ __half sm[];
    __half* sAh = sm;                // 128 x 72 halves
    __half* sAl = sm + 9216;
    __half* sBh = sm + 18432;
    __half* sBl = sm + 27648;
    uint32_t base = smem_u32(sm);

    const int tid = threadIdx.x, wid = tid >> 5, lane = tid & 31;
    const int n0 = blockIdx.x * 128, m0 = blockIdx.y * 128;

    float acc[16][4] = {};

    const int rowoff = wid * 16 + (lane & 7) + ((lane >> 3) & 1) * 8;
    const int coloff = (lane >> 4) << 3;

    // per-lane ldmatrix row base for B: row-in-pair + k-half select
    const uint32_t brow = (uint32_t)(((lane >> 4) & 1) * 8 + (lane & 7));
    const uint32_t bkoff = (uint32_t)(((lane >> 3) & 1) * 16);
    const uint32_t lmBh = base + 36864u + brow * 144u + bkoff;   // sBh bytes
    const uint32_t lmBl = base + 55296u + brow * 144u + bkoff;   // sBl bytes

    for (int k0 = 0; k0 < HDIM; k0 += 64) {
        __syncthreads();
        #pragma unroll
        for (int i = 0; i < 4; i++) {
            int e = tid + i * 256;              // 0..1023
            int row = e >> 3, c8 = (e & 7) * 8;
            *reinterpret_cast<uint4*>(&sAh[row * 72 + c8]) =
                *reinterpret_cast<const uint4*>(&Ah[(size_t)(m0 + row) * HDIM + k0 + c8]);
            *reinterpret_cast<uint4*>(&sAl[row * 72 + c8]) =
                *reinterpret_cast<const uint4*>(&Al[(size_t)(m0 + row) * HDIM + k0 + c8]);
            *reinterpret_cast<uint4*>(&sBh[row * 72 + c8]) =
                *reinterpret_cast<const uint4*>(&Bh[(size_t)(n0 + row) * HDIM + k0 + c8]);
            *reinterpret_cast<uint4*>(&sBl[row * 72 + c8]) =
                *reinterpret_cast<const uint4*>(&Bl[(size_t)(n0 + row) * HDIM + k0 + c8]);
        }
        __syncthreads();
        #pragma unroll
        for (int kq = 0; kq < 4; kq++) {
            uint32_t ah[4], al[4];
            uint32_t addr = base + (uint32_t)(rowoff * 72 + kq * 16 + coloff) * 2u;
            ldmx4(ah, addr);
            ldmx4(al, addr + 18432u);
            #pragma unroll
            for (int p = 0; p < 8; p++) {
                uint32_t bh[4], bl[4];
                uint32_t ba = (uint32_t)(p * 16 * 144) + (uint32_t)(kq * 32);
                ldmx4(bh, lmBh + ba);
                ldmx4(bl, lmBl + ba);
                mma16816(acc[2 * p],     ah, bh[0], bh[1]);
                mma16816(acc[2 * p],     ah, bl[0], bl[1]);
                mma16816(acc[2 * p],     al, bh[0], bh[1]);
                mma16816(acc[2 * p + 1], ah, bh[2], bh[3]);
                mma16816(acc[2 * p + 1], ah, bl[2], bl[3]);
                mma16816(acc[2 * p + 1], al, bh[2], bh[3]);
            }
        }
    }

    #pragma unroll
    for (int nt = 0; nt < 16; nt++)
        #pragma unroll
        for (int c = 0; c < 4; c++) {
            int m = m0 + wid * 16 + ((c >> 1) << 3) + (lane >> 2);
            int n = n0 + nt * 8 + ((lane & 3) << 1) + (c & 1);
            C[(size_t)m * G4 + n] = acc[nt][c] + __ldg(bias + n);
        }
}

// ---------------- persistent HMMA recurrent kernel (K-split) ----------------
// 128 blocks: bid -> (jt = bid&31, ks4 = bid>>5). Block owns j [jt*128,+128),
// K [ks4*256,+256). Warp wid owns 16 j rows, full block-K (kq 0..15).
// B fragments via ldmatrix.x4 (row stride 528 B = 132 words = 4 mod 32,
// conflict-free).
__global__ void __launch_bounds__(NTHR, 1) milstm_mma(
    const float* __restrict__ gx,
    const __half* __restrict__ Uh, const __half* __restrict__ Ul,
    const float* __restrict__ lngw, const float* __restrict__ lngb,
    const float* __restrict__ lncw, const float* __restrict__ lncb,
    float* __restrict__ out)
{
    extern __shared__ char dsm[];
    uint32_t sbase = smem_u32(dsm);
    __half* hsm = reinterpret_cast<__half*>(dsm);
    float* sgx = reinterpret_cast<float*>(dsm + 33792);            // 4096 floats

    const int tid = threadIdx.x, bid = blockIdx.x;
    const int wid = tid >> 5, lane = tid & 31;
    const int jt = bid & 31, ks4 = bid >> 5;
    const int jb = jt * 128, kb = ks4 * 256;

    // ---- stage U slice (128 rows x 256 K, hi+lo) into smem once ----
    #pragma unroll
    for (int i = 0; i < 16; i++) {
        int e = tid + i * NTHR;                 // 0..4095 uint4
        int row = e >> 5, c8 = (e & 31) * 8;
        *reinterpret_cast<uint4*>(&hsm[row * 264 + c8]) =
            *reinterpret_cast<const uint4*>(&Uh[(size_t)(jb + row) * HDIM + kb + c8]);
        *reinterpret_cast<uint4*>(&hsm[33792 + row * 264 + c8]) =
            *reinterpret_cast<const uint4*>(&Ul[(size_t)(jb + row) * HDIM + kb + c8]);
    }
    __syncthreads();

    // ---- preload U A-fragments (hi+lo) ----
    uint32_t afrh[16][4], afrl[16][4];
    {
        int rowoff = wid * 16 + (lane & 7) + ((lane >> 3) & 1) * 8;
        int coloff = (lane >> 4) << 3;
        #pragma unroll
        for (int kq = 0; kq < 16; kq++) {
            uint32_t addr = sbase + (uint32_t)(rowoff * 264 + kq * 16 + coloff) * 2u;
            ldmx4(afrh[kq], addr);
            ldmx4(afrl[kq], addr + 67584u);
        }
    }
    __syncthreads();

    // ---- zero-init recurrent state ----
    {
        int i = bid * NTHR + tid;               // covers 32768 = BATCH*HDIM
        g_c[i] = 0.0f;
        g_hh[i] = __float2half(0.0f);
        g_hl[i] = __float2half(0.0f);
    }
    grid_sync();

    // phase-B per-thread constants
    const int j4 = tid * 4;
    float4 lw[4], lb[4];
    #pragma unroll
    for (int s = 0; s < 4; s++) {
        lw[s] = *(const float4*)(lngw + s * 1024 + j4);
        lb[s] = *(const float4*)(lngb + s * 1024 + j4);
    }
    float4 cw = *(const float4*)(lncw + j4);
    float4 cb = *(const float4*)(lncb + j4);

    // per-lane ldmatrix bases for h B-fragments (2 nt-pairs x hi/lo)
    const uint32_t hrow = (uint32_t)(((lane >> 4) & 1) * 8 + (lane & 7));
    const uint32_t hkoff = (uint32_t)(((lane >> 3) & 1) * 16);
    const uint32_t lmH0 = sbase + hrow * 528u + hkoff;              // pair 0, hi
    const uint32_t lmH1 = sbase + (16u + hrow) * 528u + hkoff;      // pair 1, hi
    const uint32_t lmL0 = lmH0 + 16896u;                            // lo
    const uint32_t lmL1 = lmH1 + 16896u;

    for (int t = 0; t < TSEQ; ++t) {
        // ---- gx prefetch for phase B (own slice only; self-consumed) ----
        if (bid < BATCH) {
            const char* src = (const char*)(gx + ((size_t)bid * TSEQ + t) * G4);
            #pragma unroll
            for (int i = 0; i < 4; i++)
                cp16(sbase + 33792u + (uint32_t)(tid * 16 + i * 4096),
                     src + tid * 16 + i * 4096);
            cp_commit();
        }

        // ---- stage h slice (32 r x 256 K, hi+lo) ----
        #pragma unroll
        for (int i = 0; i < 4; i++) {
            int e = tid + i * NTHR;             // 0..1023 uint4
            int row = e >> 5, c8 = (e & 31) * 8;
            *reinterpret_cast<uint4*>(&hsm[row * 264 + c8]) =
                *reinterpret_cast<const uint4*>(&g_hh[row * HDIM + kb + c8]);
            *reinterpret_cast<uint4*>(&hsm[8448 + row * 264 + c8]) =
                *reinterpret_cast<const uint4*>(&g_hl[row * HDIM + kb + c8]);
        }
        __syncthreads();

        // ---- 3-pass MMA over block-K slice (ldmatrix B loads) ----
        float acc[4][4] = {};
        #pragma unroll
        for (int kq = 0; kq < 16; kq++) {
            uint32_t ka = (uint32_t)(kq * 32);
            uint32_t bh[8], bl[8];
            ldmx4(bh,     lmH0 + ka);
            ldmx4(bh + 4, lmH1 + ka);
            ldmx4(bl,     lmL0 + ka);
            ldmx4(bl + 4, lmL1 + ka);
            #pragma unroll
            for (int nt = 0; nt < 4; nt++) {
                mma16816(acc[nt], afrh[kq], bh[2 * nt], bh[2 * nt + 1]);
                mma16816(acc[nt], afrh[kq], bl[2 * nt], bl[2 * nt + 1]);
                mma16816(acc[nt], afrl[kq], bh[2 * nt], bh[2 * nt + 1]);
            }
        }
        __syncthreads();   // hs reads done before next-step overwrite

        // ---- store partials directly: g_ghp[ks4][r][j] ----
        #pragma unroll
        for (int nt = 0; nt < 4; nt++)
            #pragma unroll
            for (int c = 0; c < 4; c++) {
                int jl = wid * 16 + ((c >> 1) << 3) + (lane >> 2);
                int r = nt * 8 + ((lane & 3) << 1) + (c & 1);
                g_ghp[(size_t)(ks4 * 32 + r) * G4 + jb + jl] = acc[nt][c];
            }
        grid_sync();

        // ---- phase B: blocks 0..31, one batch row each ----
        if (bid < BATCH) {
            cp_wait0();
            const int r = bid;
            float v[4][4];
            float s = 0.0f, s2 = 0.0f;
            #pragma unroll
            for (int sec = 0; sec < 4; sec++) {
                size_t off = (size_t)r * G4 + sec * 1024 + j4;
                float4 a0 = *(const float4*)&g_ghp[off];
                float4 a1 = *(const float4*)&g_ghp[off + 32ULL * G4];
                float4 a2 = *(const float4*)&g_ghp[off + 64ULL * G4];
                float4 a3 = *(const float4*)&g_ghp[off + 96ULL * G4];
                float4 xv = *(const float4*)(sgx + sec * 1024 + j4);
                float gh0 = a0.x + a1.x + a2.x + a3.x;
                float gh1 = a0.y + a1.y + a2.y + a3.y;
                float gh2 = a0.z + a1.z + a2.z + a3.z;
                float gh3 = a0.w + a1.w + a2.w + a3.w;
                v[sec][0] = xv.x + gh0 + xv.x * gh0;
                v[sec][1] = xv.y + gh1 + xv.y * gh1;
                v[sec][2] = xv.z + gh2 + xv.z * gh2;
                v[sec][3] = xv.w + gh3 + xv.w * gh3;
                #pragma unroll
                for (int q = 0; q < 4; q++) { s += v[sec][q]; s2 += v[sec][q] * v[sec][q]; }
            }
            float2 tot = reduce2(s, s2);
            float mean = tot.x * (1.0f / G4);
            float var  = tot.y * (1.0f / G4) - mean * mean;
            float rstd = rsqrtf(var + 1e-5f);

            float4 cprev = *(const float4*)(g_c + r * HDIM + j4);
            const float* pcp = &cprev.x;
            float ov[4], cv[4];
            float cs = 0.0f, cs2 = 0.0f;
            #pragma unroll
            for (int q = 0; q < 4; q++) {
                const float* pw0 = &lw[0].x; const float* pb0 = &lb[0].x;
                const float* pw1 = &lw[1].x; const float* pb1 = &lb[1].x;
                const float* pw2 = &lw[2].x; const float* pb2 = &lb[2].x;
                const float* pw3 = &lw[3].x; const float* pb3 = &lb[3].x;
                float gi = (v[0][q] - mean) * rstd * pw0[q] + pb0[q];
                float gf = (v[1][q] - mean) * rstd * pw1[q] + pb1[q];
                float gg = (v[2][q] - mean) * rstd * pw2[q] + pb2[q];
                float go = (v[3][q] - mean) * rstd * pw3[q] + pb3[q];
                float ivv = sigmoidf_(gi);
                float fvv = sigmoidf_(gf);
                float gvv = ftanh(gg);
                ov[q] = sigmoidf_(go);
                float c = fvv * pcp[q] + ivv * gvv;
                cv[q] = c;
                cs += c; cs2 += c * c;
            }
            float2 ct = reduce2(cs, cs2);
            float cm   = ct.x * (1.0f / HDIM);
            float cvar = ct.y * (1.0f / HDIM) - cm * cm;
            float crs  = rsqrtf(cvar + 1e-5f);
            const float* pcw = &cw.x; const float* pcb = &cb.x;
            float4 cno, hno;
            float* pcn = &cno.x; float* phn = &hno.x;
            #pragma unroll
            for (int q = 0; q < 4; q++) {
                float cn = (cv[q] - cm) * crs * pcw[q] + pcb[q];
                pcn[q] = cn;
                phn[q] = ov[q] * ftanh(cn);
            }
            *(float4*)(g_c + r * HDIM + j4) = cno;
            *(float4*)(out + ((size_t)r * TSEQ + t) * HDIM + j4) = hno;
            __half hh0 = __float2half_rn(hno.x);
            __half hh1 = __float2half_rn(hno.y);
            __half hh2 = __float2half_rn(hno.z);
            __half hh3 = __float2half_rn(hno.w);
            __half hl0 = __float2half_rn(hno.x - __half2float(hh0));
            __half hl1 = __float2half_rn(hno.y - __half2float(hh1));
            __half hl2 = __float2half_rn(hno.z - __half2float(hh2));
            __half hl3 = __float2half_rn(hno.w - __half2float(hh3));
            *reinterpret_cast<__half2*>(g_hh + r * HDIM + j4)     = __halves2half2(hh0, hh1);
            *reinterpret_cast<__half2*>(g_hh + r * HDIM + j4 + 2) = __halves2half2(hh2, hh3);
            *reinterpret_cast<__half2*>(g_hl + r * HDIM + j4)     = __halves2half2(hl0, hl1);
            *reinterpret_cast<__half2*>(g_hl + r * HDIM + j4 + 2) = __halves2half2(hl2, hl3);
        }
        grid_sync();
    }
}

// ---------------- launch ----------------
extern "C" void kernel_launch(void* const* d_in, const int* in_sizes, int n_in,
                              void* d_out, int out_size) {
    const float* x    = (const float*)d_in[0];
    const float* W    = (const float*)d_in[1];
    const float* b    = (const float*)d_in[2];
    const float* U    = (const float*)d_in[3];
    const float* lngw = (const float*)d_in[4];
    const float* lngb = (const float*)d_in[5];
    const float* lncw = (const float*)d_in[6];
    const float* lncb = (const float*)d_in[7];
    float* y = (float*)d_out;

    cudaFuncSetAttribute(milstm_mma, cudaFuncAttributeMaxDynamicSharedMemorySize,
                         SMEM_DYN);
    cudaFuncSetAttribute(sgemm_hmma, cudaFuncAttributeMaxDynamicSharedMemorySize,
                         SMEM_GEMM);

    float *gx, *h0;
    cudaGetSymbolAddress((void**)&gx, g_gx);
    cudaGetSymbolAddress((void**)&h0, g_h0);
    __half *Uh, *Ul, *Wh, *Wl, *Ah, *Al;
    cudaGetSymbolAddress((void**)&Uh, g_Uh);
    cudaGetSymbolAddress((void**)&Ul, g_Ul);
    cudaGetSymbolAddress((void**)&Wh, g_Wh);
    cudaGetSymbolAddress((void**)&Wl, g_Wl);
    cudaGetSymbolAddress((void**)&Ah, g_Ah);
    cudaGetSymbolAddress((void**)&Al, g_Al);

    const size_t WSZ = 2ULL * G4 * HDIM;
    const size_t ASZ = (size_t)BATCH * TSEQ * HDIM;
    const size_t LOFF = (size_t)G4 * HDIM;

    pack_hilo<<<1024, 256>>>(U, Uh, Ul, WSZ);
    pack_hilo<<<1024, 256>>>(W, Wh, Wl, WSZ);
    pack_hilo<<<1024, 256>>>(x, Ah, Al, ASZ);

    dim3 gg(G4 / 128, BATCH * TSEQ / 128);   // (32, 128)

    // layer 0
    sgemm_hmma<<<gg, 256, SMEM_GEMM>>>(Ah, Al, Wh, Wl, b, gx);
    milstm_mma<<<NBLK, NTHR, SMEM_DYN>>>(gx, Uh, Ul, lngw, lngb, lncw, lncb, h0);
    // layer 1
    pack_hilo<<<1024, 256>>>(h0, Ah, Al, ASZ);
    sgemm_hmma<<<gg, 256, SMEM_GEMM>>>(Ah, Al, Wh + LOFF, Wl + LOFF, b + G4, gx);
    milstm_mma<<<NBLK, NTHR, SMEM_DYN>>>(gx, Uh + LOFF, Ul + LOFF,
                                         lngw + G4, lngb + G4,
                                         lncw + HDIM, lncb + HDIM, y);
}

// round 13
// speedup vs baseline: 3.5318x; 1.0262x over previous
#include <cuda_runtime.h>
#include <cuda_fp16.h>
#include <cstdint>

#define BATCH 32
#define TSEQ  512
#define HDIM  1024
#define G4    4096
#define NBLK  128
#define NTHR  256
#define SMEM_DYN  135168      // milstm: U-stage 2x(128x264x2B)
#define SMEM_GEMM 73728       // sgemm: 4 tiles of 128x72 halves

// ---------------- scratch (device globals; no allocation allowed) ----------------
__device__ float g_gx[(size_t)BATCH * TSEQ * G4];    // 256 MB
__device__ float g_ghp[4ULL * BATCH * G4];           // K-split partials, [ks][r][j]
__device__ float g_c[BATCH * HDIM];
__device__ __half g_hh[BATCH * HDIM];                // h state fp16 hi
__device__ __half g_hl[BATCH * HDIM];                // h state fp16 lo
__device__ __half g_Uh[2ULL * G4 * HDIM];            // U fp16 hi
__device__ __half g_Ul[2ULL * G4 * HDIM];            // U fp16 lo
__device__ __half g_Wh[2ULL * G4 * HDIM];            // W fp16 hi
__device__ __half g_Wl[2ULL * G4 * HDIM];            // W fp16 lo
__device__ __half g_Ah[(size_t)BATCH * TSEQ * HDIM]; // GEMM A fp16 hi (x or h0)
__device__ __half g_Al[(size_t)BATCH * TSEQ * HDIM]; // GEMM A fp16 lo
__device__ unsigned g_barcnt = 0;
__device__ volatile unsigned g_bargen = 0;

// ---------------- helpers ----------------
__device__ __forceinline__ float sigmoidf_(float x) {
    return 1.0f / (1.0f + __expf(-x));
}
// fast tanh: 1 - 2/(e^{2x}+1); MUFU-based, rel err ~1e-6, saturates correctly
__device__ __forceinline__ float ftanh(float x) {
    float e = __expf(2.0f * x);
    return 1.0f - 2.0f / (e + 1.0f);
}
__device__ __forceinline__ uint32_t smem_u32(const void* p) {
    uint32_t a;
    asm("{ .reg .u64 t; cvta.to.shared.u64 t, %1; cvt.u32.u64 %0, t; }" : "=r"(a) : "l"(p));
    return a;
}
__device__ __forceinline__ void ldmx4(uint32_t* r, uint32_t addr) {
    asm volatile("ldmatrix.sync.aligned.m8n8.x4.shared.b16 {%0,%1,%2,%3}, [%4];"
                 : "=r"(r[0]), "=r"(r[1]), "=r"(r[2]), "=r"(r[3]) : "r"(addr));
}
__device__ __forceinline__ void mma16816(float* c, const uint32_t* a,
                                         uint32_t b0, uint32_t b1) {
    asm volatile(
        "mma.sync.aligned.m16n8k16.row.col.f32.f16.f16.f32 "
        "{%0,%1,%2,%3}, {%4,%5,%6,%7}, {%8,%9}, {%0,%1,%2,%3};"
        : "+f"(c[0]), "+f"(c[1]), "+f"(c[2]), "+f"(c[3])
        : "r"(a[0]), "r"(a[1]), "r"(a[2]), "r"(a[3]), "r"(b0), "r"(b1));
}
__device__ __forceinline__ void cp16(uint32_t dst, const void* src) {
    asm volatile("cp.async.cg.shared.global [%0], [%1], 16;" :: "r"(dst), "l"(src));
}
__device__ __forceinline__ void cp_commit() {
    asm volatile("cp.async.commit_group;" ::: "memory");
}
__device__ __forceinline__ void cp_wait0() {
    asm volatile("cp.async.wait_group 0;" ::: "memory");
}

// grid-wide barrier; all NBLK blocks co-resident (1 block/SM by smem usage).
// Poll with nanosleep backoff to keep the release line from being swamped.
__device__ __forceinline__ void grid_sync() {
    __threadfence();
    __syncthreads();
    if (threadIdx.x == 0) {
        unsigned gen = g_bargen;
        if (atomicAdd(&g_barcnt, 1u) == NBLK - 1u) {
            g_barcnt = 0u;
            __threadfence();
            g_bargen = gen + 1u;
        } else {
            if (g_bargen == gen) {
                while (g_bargen == gen) { __nanosleep(40); }
            }
            __threadfence();
        }
    }
    __syncthreads();
}

// block-wide 2-value sum reduce
__device__ __forceinline__ float2 reduce2(float a, float b) {
    __shared__ float sA[8], sB[8];
    __syncthreads();
    #pragma unroll
    for (int o = 16; o > 0; o >>= 1) {
        a += __shfl_xor_sync(0xFFFFFFFFu, a, o);
        b += __shfl_xor_sync(0xFFFFFFFFu, b, o);
    }
    int wid = threadIdx.x >> 5, lid = threadIdx.x & 31;
    if (lid == 0) { sA[wid] = a; sB[wid] = b; }
    __syncthreads();
    if (threadIdx.x < 32) {
        a = (lid < 8) ? sA[lid] : 0.0f;
        b = (lid < 8) ? sB[lid] : 0.0f;
        #pragma unroll
        for (int o = 4; o > 0; o >>= 1) {
            a += __shfl_xor_sync(0xFFFFFFFFu, a, o);
            b += __shfl_xor_sync(0xFFFFFFFFu, b, o);
        }
        if (lid == 0) { sA[0] = a; sB[0] = b; }
    }
    __syncthreads();
    return make_float2(sA[0], sB[0]);
}

// ---------------- pack kernels: fp32 -> fp16 hi/lo ----------------
__global__ void pack_hilo(const float* __restrict__ src, __half* __restrict__ dh,
                          __half* __restrict__ dl, size_t total) {
    for (size_t i = (size_t)blockIdx.x * blockDim.x + threadIdx.x; i < total;
         i += (size_t)gridDim.x * blockDim.x) {
        float v = src[i];
        __half hi = __float2half_rn(v);
        dh[i] = hi;
        dl[i] = __float2half_rn(v - __half2float(hi));
    }
}

// ---------------- HMMA big GEMM: C[16384,4096] = A @ B^T + bias ----------------
// 3-pass fp16 hi/lo. Tiles 128(m) x 128(n), BK=64, 256 threads, 2 blocks/SM.
// B fragments via ldmatrix.x4; MMA passes interleaved across accumulators to
// avoid back-to-back same-acc RAW chains.
__global__ void __launch_bounds__(256, 2) sgemm_hmma(
    const __half* __restrict__ Ah, const __half* __restrict__ Al,
    const __half* __restrict__ Bh, const __half* __restrict__ Bl,
    const float* __restrict__ bias, float* __restrict__ C)
{
    extern __shared__ __half sm[];
    __half* sAh = sm;                // 128 x 72 halves
    __half* sAl = sm + 9216;
    __half* sBh = sm + 18432;
    __half* sBl = sm + 27648;
    uint32_t base = smem_u32(sm);

    const int tid = threadIdx.x, wid = tid >> 5, lane = tid & 31;
    const int n0 = blockIdx.x * 128, m0 = blockIdx.y * 128;

    float acc[16][4] = {};

    const int rowoff = wid * 16 + (lane & 7) + ((lane >> 3) & 1) * 8;
    const int coloff = (lane >> 4) << 3;

    const uint32_t brow = (uint32_t)(((lane >> 4) & 1) * 8 + (lane & 7));
    const uint32_t bkoff = (uint32_t)(((lane >> 3) & 1) * 16);
    const uint32_t lmBh = base + 36864u + brow * 144u + bkoff;   // sBh bytes
    const uint32_t lmBl = base + 55296u + brow * 144u + bkoff;   // sBl bytes

    for (int k0 = 0; k0 < HDIM; k0 += 64) {
        __syncthreads();
        #pragma unroll
        for (int i = 0; i < 4; i++) {
            int e = tid + i * 256;              // 0..1023
            int row = e >> 3, c8 = (e & 7) * 8;
            *reinterpret_cast<uint4*>(&sAh[row * 72 + c8]) =
                *reinterpret_cast<const uint4*>(&Ah[(size_t)(m0 + row) * HDIM + k0 + c8]);
            *reinterpret_cast<uint4*>(&sAl[row * 72 + c8]) =
                *reinterpret_cast<const uint4*>(&Al[(size_t)(m0 + row) * HDIM + k0 + c8]);
            *reinterpret_cast<uint4*>(&sBh[row * 72 + c8]) =
                *reinterpret_cast<const uint4*>(&Bh[(size_t)(n0 + row) * HDIM + k0 + c8]);
            *reinterpret_cast<uint4*>(&sBl[row * 72 + c8]) =
                *reinterpret_cast<const uint4*>(&Bl[(size_t)(n0 + row) * HDIM + k0 + c8]);
        }
        __syncthreads();
        #pragma unroll
        for (int kq = 0; kq < 4; kq++) {
            uint32_t ah[4], al[4];
            uint32_t addr = base + (uint32_t)(rowoff * 72 + kq * 16 + coloff) * 2u;
            ldmx4(ah, addr);
            ldmx4(al, addr + 18432u);
            #pragma unroll
            for (int p = 0; p < 8; p++) {
                uint32_t bh[4], bl[4];
                uint32_t ba = (uint32_t)(p * 16 * 144) + (uint32_t)(kq * 32);
                ldmx4(bh, lmBh + ba);
                ldmx4(bl, lmBl + ba);
                mma16816(acc[2 * p],     ah, bh[0], bh[1]);
                mma16816(acc[2 * p + 1], ah, bh[2], bh[3]);
                mma16816(acc[2 * p],     ah, bl[0], bl[1]);
                mma16816(acc[2 * p + 1], ah, bl[2], bl[3]);
                mma16816(acc[2 * p],     al, bh[0], bh[1]);
                mma16816(acc[2 * p + 1], al, bh[2], bh[3]);
            }
        }
    }

    #pragma unroll
    for (int nt = 0; nt < 16; nt++)
        #pragma unroll
        for (int c = 0; c < 4; c++) {
            int m = m0 + wid * 16 + ((c >> 1) << 3) + (lane >> 2);
            int n = n0 + nt * 8 + ((lane & 3) << 1) + (c & 1);
            C[(size_t)m * G4 + n] = acc[nt][c] + __ldg(bias + n);
        }
}

// ---------------- persistent HMMA recurrent kernel (K-split) ----------------
// 128 blocks: bid -> (jt = bid&31, ks4 = bid>>5). Block owns j [jt*128,+128),
// K [ks4*256,+256). MMA passes interleaved across nt accumulators.
// Layer 0 writes h directly as fp16 hi/lo into the sgemm A-layout (outh/outl);
// layer 1 writes fp32 y (out).
__global__ void __launch_bounds__(NTHR, 1) milstm_mma(
    const float* __restrict__ gx,
    const __half* __restrict__ Uh, const __half* __restrict__ Ul,
    const float* __restrict__ lngw, const float* __restrict__ lngb,
    const float* __restrict__ lncw, const float* __restrict__ lncb,
    float* __restrict__ out, __half* __restrict__ outh, __half* __restrict__ outl)
{
    extern __shared__ char dsm[];
    uint32_t sbase = smem_u32(dsm);
    __half* hsm = reinterpret_cast<__half*>(dsm);
    float* sgx = reinterpret_cast<float*>(dsm + 33792);            // 4096 floats

    const int tid = threadIdx.x, bid = blockIdx.x;
    const int wid = tid >> 5, lane = tid & 31;
    const int jt = bid & 31, ks4 = bid >> 5;
    const int jb = jt * 128, kb = ks4 * 256;

    // ---- stage U slice (128 rows x 256 K, hi+lo) into smem once ----
    #pragma unroll
    for (int i = 0; i < 16; i++) {
        int e = tid + i * NTHR;                 // 0..4095 uint4
        int row = e >> 5, c8 = (e & 31) * 8;
        *reinterpret_cast<uint4*>(&hsm[row * 264 + c8]) =
            *reinterpret_cast<const uint4*>(&Uh[(size_t)(jb + row) * HDIM + kb + c8]);
        *reinterpret_cast<uint4*>(&hsm[33792 + row * 264 + c8]) =
            *reinterpret_cast<const uint4*>(&Ul[(size_t)(jb + row) * HDIM + kb + c8]);
    }
    __syncthreads();

    // ---- preload U A-fragments (hi+lo) ----
    uint32_t afrh[16][4], afrl[16][4];
    {
        int rowoff = wid * 16 + (lane & 7) + ((lane >> 3) & 1) * 8;
        int coloff = (lane >> 4) << 3;
        #pragma unroll
        for (int kq = 0; kq < 16; kq++) {
            uint32_t addr = sbase + (uint32_t)(rowoff * 264 + kq * 16 + coloff) * 2u;
            ldmx4(afrh[kq], addr);
            ldmx4(afrl[kq], addr + 67584u);
        }
    }
    __syncthreads();

    // ---- zero-init recurrent state ----
    {
        int i = bid * NTHR + tid;               // covers 32768 = BATCH*HDIM
        g_c[i] = 0.0f;
        g_hh[i] = __float2half(0.0f);
        g_hl[i] = __float2half(0.0f);
    }
    grid_sync();

    // phase-B per-thread constants
    const int j4 = tid * 4;
    float4 lw[4], lb[4];
    #pragma unroll
    for (int s = 0; s < 4; s++) {
        lw[s] = *(const float4*)(lngw + s * 1024 + j4);
        lb[s] = *(const float4*)(lngb + s * 1024 + j4);
    }
    float4 cw = *(const float4*)(lncw + j4);
    float4 cb = *(const float4*)(lncb + j4);

    // per-lane ldmatrix bases for h B-fragments (2 nt-pairs x hi/lo)
    const uint32_t hrow = (uint32_t)(((lane >> 4) & 1) * 8 + (lane & 7));
    const uint32_t hkoff = (uint32_t)(((lane >> 3) & 1) * 16);
    const uint32_t lmH0 = sbase + hrow * 528u + hkoff;              // pair 0, hi
    const uint32_t lmH1 = sbase + (16u + hrow) * 528u + hkoff;      // pair 1, hi
    const uint32_t lmL0 = lmH0 + 16896u;                            // lo
    const uint32_t lmL1 = lmH1 + 16896u;

    for (int t = 0; t < TSEQ; ++t) {
        // ---- gx prefetch for phase B (own slice only; self-consumed) ----
        if (bid < BATCH) {
            const char* src = (const char*)(gx + ((size_t)bid * TSEQ + t) * G4);
            #pragma unroll
            for (int i = 0; i < 4; i++)
                cp16(sbase + 33792u + (uint32_t)(tid * 16 + i * 4096),
                     src + tid * 16 + i * 4096);
            cp_commit();
        }

        // ---- stage h slice (32 r x 256 K, hi+lo) ----
        #pragma unroll
        for (int i = 0; i < 4; i++) {
            int e = tid + i * NTHR;             // 0..1023 uint4
            int row = e >> 5, c8 = (e & 31) * 8;
            *reinterpret_cast<uint4*>(&hsm[row * 264 + c8]) =
                *reinterpret_cast<const uint4*>(&g_hh[row * HDIM + kb + c8]);
            *reinterpret_cast<uint4*>(&hsm[8448 + row * 264 + c8]) =
                *reinterpret_cast<const uint4*>(&g_hl[row * HDIM + kb + c8]);
        }
        __syncthreads();

        // ---- 3-pass MMA over block-K slice (pass-major: no same-acc chains) ----
        float acc[4][4] = {};
        #pragma unroll
        for (int kq = 0; kq < 16; kq++) {
            uint32_t ka = (uint32_t)(kq * 32);
            uint32_t bh[8], bl[8];
            ldmx4(bh,     lmH0 + ka);
            ldmx4(bh + 4, lmH1 + ka);
            ldmx4(bl,     lmL0 + ka);
            ldmx4(bl + 4, lmL1 + ka);
            #pragma unroll
            for (int nt = 0; nt < 4; nt++)
                mma16816(acc[nt], afrh[kq], bh[2 * nt], bh[2 * nt + 1]);
            #pragma unroll
            for (int nt = 0; nt < 4; nt++)
                mma16816(acc[nt], afrh[kq], bl[2 * nt], bl[2 * nt + 1]);
            #pragma unroll
            for (int nt = 0; nt < 4; nt++)
                mma16816(acc[nt], afrl[kq], bh[2 * nt], bh[2 * nt + 1]);
        }
        __syncthreads();   // hs reads done before next-step overwrite

        // ---- store partials directly: g_ghp[ks4][r][j] ----
        #pragma unroll
        for (int nt = 0; nt < 4; nt++)
            #pragma unroll
            for (int c = 0; c < 4; c++) {
                int jl = wid * 16 + ((c >> 1) << 3) + (lane >> 2);
                int r = nt * 8 + ((lane & 3) << 1) + (c & 1);
                g_ghp[(size_t)(ks4 * 32 + r) * G4 + jb + jl] = acc[nt][c];
            }
        grid_sync();

        // ---- phase B: blocks 0..31, one batch row each ----
        if (bid < BATCH) {
            cp_wait0();
            const int r = bid;
            float v[4][4];
            float s = 0.0f, s2 = 0.0f;
            #pragma unroll
            for (int sec = 0; sec < 4; sec++) {
                size_t off = (size_t)r * G4 + sec * 1024 + j4;
                float4 a0 = *(const float4*)&g_ghp[off];
                float4 a1 = *(const float4*)&g_ghp[off + 32ULL * G4];
                float4 a2 = *(const float4*)&g_ghp[off + 64ULL * G4];
                float4 a3 = *(const float4*)&g_ghp[off + 96ULL * G4];
                float4 xv = *(const float4*)(sgx + sec * 1024 + j4);
                float gh0 = a0.x + a1.x + a2.x + a3.x;
                float gh1 = a0.y + a1.y + a2.y + a3.y;
                float gh2 = a0.z + a1.z + a2.z + a3.z;
                float gh3 = a0.w + a1.w + a2.w + a3.w;
                v[sec][0] = xv.x + gh0 + xv.x * gh0;
                v[sec][1] = xv.y + gh1 + xv.y * gh1;
                v[sec][2] = xv.z + gh2 + xv.z * gh2;
                v[sec][3] = xv.w + gh3 + xv.w * gh3;
                #pragma unroll
                for (int q = 0; q < 4; q++) { s += v[sec][q]; s2 += v[sec][q] * v[sec][q]; }
            }
            float2 tot = reduce2(s, s2);
            float mean = tot.x * (1.0f / G4);
            float var  = tot.y * (1.0f / G4) - mean * mean;
            float rstd = rsqrtf(var + 1e-5f);

            float4 cprev = *(const float4*)(g_c + r * HDIM + j4);
            const float* pcp = &cprev.x;
            float ov[4], cv[4];
            float cs = 0.0f, cs2 = 0.0f;
            #pragma unroll
            for (int q = 0; q < 4; q++) {
                const float* pw0 = &lw[0].x; const float* pb0 = &lb[0].x;
                const float* pw1 = &lw[1].x; const float* pb1 = &lb[1].x;
                const float* pw2 = &lw[2].x; const float* pb2 = &lb[2].x;
                const float* pw3 = &lw[3].x; const float* pb3 = &lb[3].x;
                float gi = (v[0][q] - mean) * rstd * pw0[q] + pb0[q];
                float gf = (v[1][q] - mean) * rstd * pw1[q] + pb1[q];
                float gg = (v[2][q] - mean) * rstd * pw2[q] + pb2[q];
                float go = (v[3][q] - mean) * rstd * pw3[q] + pb3[q];
                float ivv = sigmoidf_(gi);
                float fvv = sigmoidf_(gf);
                float gvv = ftanh(gg);
                ov[q] = sigmoidf_(go);
                float c = fvv * pcp[q] + ivv * gvv;
                cv[q] = c;
                cs += c; cs2 += c * c;
            }
            float2 ct = reduce2(cs, cs2);
            float cm   = ct.x * (1.0f / HDIM);
            float cvar = ct.y * (1.0f / HDIM) - cm * cm;
            float crs  = rsqrtf(cvar + 1e-5f);
            const float* pcw = &cw.x; const float* pcb = &cb.x;
            float4 cno, hno;
            float* pcn = &cno.x; float* phn = &hno.x;
            #pragma unroll
            for (int q = 0; q < 4; q++) {
                float cn = (cv[q] - cm) * crs * pcw[q] + pcb[q];
                pcn[q] = cn;
                phn[q] = ov[q] * ftanh(cn);
            }
            *(float4*)(g_c + r * HDIM + j4) = cno;
            __half hh0 = __float2half_rn(hno.x);
            __half hh1 = __float2half_rn(hno.y);
            __half hh2 = __float2half_rn(hno.z);
            __half hh3 = __float2half_rn(hno.w);
            __half hl0 = __float2half_rn(hno.x - __half2float(hh0));
            __half hl1 = __float2half_rn(hno.y - __half2float(hh1));
            __half hl2 = __float2half_rn(hno.z - __half2float(hh2));
            __half hl3 = __float2half_rn(hno.w - __half2float(hh3));
            *reinterpret_cast<__half2*>(g_hh + r * HDIM + j4)     = __halves2half2(hh0, hh1);
            *reinterpret_cast<__half2*>(g_hh + r * HDIM + j4 + 2) = __halves2half2(hh2, hh3);
            *reinterpret_cast<__half2*>(g_hl + r * HDIM + j4)     = __halves2half2(hl0, hl1);
            *reinterpret_cast<__half2*>(g_hl + r * HDIM + j4 + 2) = __halves2half2(hl2, hl3);
            size_t obase = ((size_t)r * TSEQ + t) * HDIM + j4;
            if (out) {
                *(float4*)(out + obase) = hno;
            } else {
                *reinterpret_cast<__half2*>(outh + obase)     = __halves2half2(hh0, hh1);
                *reinterpret_cast<__half2*>(outh + obase + 2) = __halves2half2(hh2, hh3);
                *reinterpret_cast<__half2*>(outl + obase)     = __halves2half2(hl0, hl1);
                *reinterpret_cast<__half2*>(outl + obase + 2) = __halves2half2(hl2, hl3);
            }
        }
        grid_sync();
    }
}

// ---------------- launch ----------------
extern "C" void kernel_launch(void* const* d_in, const int* in_sizes, int n_in,
                              void* d_out, int out_size) {
    const float* x    = (const float*)d_in[0];
    const float* W    = (const float*)d_in[1];
    const float* b    = (const float*)d_in[2];
    const float* U    = (const float*)d_in[3];
    const float* lngw = (const float*)d_in[4];
    const float* lngb = (const float*)d_in[5];
    const float* lncw = (const float*)d_in[6];
    const float* lncb = (const float*)d_in[7];
    float* y = (float*)d_out;

    cudaFuncSetAttribute(milstm_mma, cudaFuncAttributeMaxDynamicSharedMemorySize,
                         SMEM_DYN);
    cudaFuncSetAttribute(sgemm_hmma, cudaFuncAttributeMaxDynamicSharedMemorySize,
                         SMEM_GEMM);

    float *gx;
    cudaGetSymbolAddress((void**)&gx, g_gx);
    __half *Uh, *Ul, *Wh, *Wl, *Ah, *Al;
    cudaGetSymbolAddress((void**)&Uh, g_Uh);
    cudaGetSymbolAddress((void**)&Ul, g_Ul);
    cudaGetSymbolAddress((void**)&Wh, g_Wh);
    cudaGetSymbolAddress((void**)&Wl, g_Wl);
    cudaGetSymbolAddress((void**)&Ah, g_Ah);
    cudaGetSymbolAddress((void**)&Al, g_Al);

    const size_t WSZ = 2ULL * G4 * HDIM;
    const size_t ASZ = (size_t)BATCH * TSEQ * HDIM;
    const size_t LOFF = (size_t)G4 * HDIM;

    pack_hilo<<<1024, 256>>>(U, Uh, Ul, WSZ);
    pack_hilo<<<1024, 256>>>(W, Wh, Wl, WSZ);
    pack_hilo<<<1024, 256>>>(x, Ah, Al, ASZ);

    dim3 gg(G4 / 128, BATCH * TSEQ / 128);   // (32, 128)

    // layer 0 (h written straight to Ah/Al in sgemm A-layout)
    sgemm_hmma<<<gg, 256, SMEM_GEMM>>>(Ah, Al, Wh, Wl, b, gx);
    milstm_mma<<<NBLK, NTHR, SMEM_DYN>>>(gx, Uh, Ul, lngw, lngb, lncw, lncb,
                                         nullptr, Ah, Al);
    // layer 1
    sgemm_hmma<<<gg, 256, SMEM_GEMM>>>(Ah, Al, Wh + LOFF, Wl + LOFF, b + G4, gx);
    milstm_mma<<<NBLK, NTHR, SMEM_DYN>>>(gx, Uh + LOFF, Ul + LOFF,
                                         lngw + G4, lngb + G4,
                                         lncw + HDIM, lncb + HDIM, y,
                                         nullptr, nullptr);
}